// round 12
// baseline (speedup 1.0000x reference)
#include <cuda_runtime.h>
#include <math.h>

#define Bsz  2
#define Nseq 2048
#define Emb  1024
#define Hh   16
#define Dh   64

// Scratch (allocation-free: __device__ globals)
__device__ float g_q [Bsz * Hh * Nseq * Dh];   // [B,H,N,D] (tf32-rounded)
__device__ float g_k [Bsz * Hh * Nseq * Dh];
__device__ float g_v [Bsz * Hh * Nseq * Dh];
__device__ float g_ao[Bsz * Nseq * Hh * Dh];   // [B,N,H*D] (tf32-rounded)
__device__ float g_x [Bsz * Nseq * Emb];       // tf32-rounded x
__device__ float g_wq[3 * Hh * Dh * Emb];      // tf32-rounded Wqkv
__device__ float g_wo[Emb * Hh * Dh];          // tf32-rounded Wout

// ---------------------------------------------------------------------------
// helpers
// ---------------------------------------------------------------------------
__device__ __forceinline__ float f2tf32(float f) {
    unsigned r;
    asm("cvt.rna.tf32.f32 %0, %1;" : "=r"(r) : "f"(f));
    return __uint_as_float(r);
}

__device__ __forceinline__ void mma_tf32(float* c, const unsigned* a, const unsigned* b) {
    asm volatile(
        "mma.sync.aligned.m16n8k8.row.col.f32.tf32.tf32.f32 "
        "{%0,%1,%2,%3},{%4,%5,%6,%7},{%8,%9},{%0,%1,%2,%3};"
        : "+f"(c[0]), "+f"(c[1]), "+f"(c[2]), "+f"(c[3])
        : "r"(a[0]), "r"(a[1]), "r"(a[2]), "r"(a[3]), "r"(b[0]), "r"(b[1]));
}

__device__ __forceinline__ void ldsm_x4(unsigned& r0, unsigned& r1, unsigned& r2, unsigned& r3,
                                        unsigned saddr) {
    asm volatile("ldmatrix.sync.aligned.m8n8.x4.shared.b16 {%0,%1,%2,%3}, [%4];"
                 : "=r"(r0), "=r"(r1), "=r"(r2), "=r"(r3) : "r"(saddr));
}

__device__ __forceinline__ void cp16(void* dst_smem, const void* src_gmem) {
    unsigned d = (unsigned)__cvta_generic_to_shared(dst_smem);
    asm volatile("cp.async.cg.shared.global [%0], [%1], 16;" :: "r"(d), "l"(src_gmem));
}

// ---------------------------------------------------------------------------
// tf32 pre-convert pass (all three tensors in one launch)
// ---------------------------------------------------------------------------
__global__ void cvt_tf32_kernel(const float4* __restrict__ x_in,  float4* __restrict__ x_out,  int n1,
                                const float4* __restrict__ wq_in, float4* __restrict__ wq_out, int n2,
                                const float4* __restrict__ wo_in, float4* __restrict__ wo_out, int n3)
{
    const int i = blockIdx.x * 256 + threadIdx.x;
    const float4* src; float4* dst; int idx;
    if (i < n1)            { src = x_in;  dst = x_out;  idx = i; }
    else if (i < n1 + n2)  { src = wq_in; dst = wq_out; idx = i - n1; }
    else if (i < n1 + n2 + n3) { src = wo_in; dst = wo_out; idx = i - n1 - n2; }
    else return;
    float4 v = src[idx];
    float4 r;
    r.x = f2tf32(v.x); r.y = f2tf32(v.y); r.z = f2tf32(v.z); r.w = f2tf32(v.w);
    dst[idx] = r;
}

// ---------------------------------------------------------------------------
// TF32 GEMM (R5 version — best measured: K1=188.4us).
// 128x128 block tile, BK=32, 256 threads = 8 warps (4 x 2), warp tile 32x64.
// cp.async 2-stage pipeline, 128B-swizzled smem, ldmatrix fragment loads.
// Dynamic smem: 2*(128*32)*2 floats = 64 KB.
// ---------------------------------------------------------------------------
template <int MODE>
__global__ void __launch_bounds__(256, 2) gemm_tf32_kernel(const float* __restrict__ bias,
                                                           float* __restrict__ out)
{
    extern __shared__ float smem[];
    float* Asm = smem;          // 2 stages x 4096 floats
    float* Wsm = smem + 8192;   // 2 stages x 4096 floats

    const float* Ain = (MODE == 0) ? g_x  : g_ao;
    const float* Win = (MODE == 0) ? g_wq : g_wo;

    const int tid  = threadIdx.x;
    const int lane = tid & 31;
    const int warp = tid >> 5;
    const int wm   = warp & 3;         // 0..3 : 32-row group
    const int wn   = warp >> 2;        // 0..1 : 64-col group
    const int bm = blockIdx.y * 128;
    const int bn = blockIdx.x * 128;

    const int gid = lane >> 2;
    const int tig = lane & 3;

    // ldmatrix per-lane address components
    const int a_row  = lane & 15;
    const int a_cbit = lane >> 4;
    const int b_row  = (lane & 7) + ((lane & 16) >> 1);
    const int b_cbit = (lane >> 3) & 1;

    float acc[2][8][4];
#pragma unroll
    for (int mi = 0; mi < 2; mi++)
#pragma unroll
        for (int nj = 0; nj < 8; nj++)
#pragma unroll
            for (int q = 0; q < 4; q++) acc[mi][nj][q] = 0.f;

    auto cp_tile = [&](int kt, int stage) {
        const float* Ab = Ain + (size_t)bm * Emb + kt * 32;
        const float* Wb = Win + (size_t)bn * Emb + kt * 32;
        float* as = Asm + stage * 4096;
        float* ws = Wsm + stage * 4096;
#pragma unroll
        for (int i = 0; i < 4; i++) {
            const int idx = tid + i * 256;          // 0..1023
            const int row = idx >> 3;               // 0..127
            const int ch  = idx & 7;                // 16B chunk
            const int off = row * 32 + ((ch ^ (row & 7)) << 2);
            cp16(as + off, Ab + (size_t)row * Emb + ch * 4);
            cp16(ws + off, Wb + (size_t)row * Emb + ch * 4);
        }
        asm volatile("cp.async.commit_group;");
    };

    const int NT = Emb / 32;
    cp_tile(0, 0);

    for (int kt = 0; kt < NT; kt++) {
        if (kt + 1 < NT) {
            cp_tile(kt + 1, (kt + 1) & 1);
            asm volatile("cp.async.wait_group 1;");
        } else {
            asm volatile("cp.async.wait_group 0;");
        }
        __syncthreads();

        const float* as = Asm + (kt & 1) * 4096;
        const float* ws = Wsm + (kt & 1) * 4096;

#pragma unroll
        for (int kk8 = 0; kk8 < 4; kk8++) {
            unsigned afrag[2][4];
#pragma unroll
            for (int mi = 0; mi < 2; mi++) {
                const int row = wm * 32 + mi * 16 + a_row;
                const int ch  = kk8 * 2 + a_cbit;
                const unsigned sa = (unsigned)__cvta_generic_to_shared(
                    as + row * 32 + ((ch ^ (row & 7)) << 2));
                ldsm_x4(afrag[mi][0], afrag[mi][1], afrag[mi][2], afrag[mi][3], sa);
            }
            unsigned bfrag[8][2];
#pragma unroll
            for (int nj2 = 0; nj2 < 4; nj2++) {
                const int row = wn * 64 + nj2 * 16 + b_row;
                const int ch  = kk8 * 2 + b_cbit;
                const unsigned sb = (unsigned)__cvta_generic_to_shared(
                    ws + row * 32 + ((ch ^ (row & 7)) << 2));
                ldsm_x4(bfrag[nj2 * 2][0], bfrag[nj2 * 2][1],
                        bfrag[nj2 * 2 + 1][0], bfrag[nj2 * 2 + 1][1], sb);
            }
#pragma unroll
            for (int mi = 0; mi < 2; mi++)
#pragma unroll
                for (int nj = 0; nj < 8; nj++)
                    mma_tf32(acc[mi][nj], afrag[mi], bfrag[nj]);
        }
        __syncthreads();
    }

    // epilogue
#pragma unroll
    for (int mi = 0; mi < 2; mi++) {
        const int r_top = bm + wm * 32 + mi * 16 + gid;
        const int r_bot = r_top + 8;
#pragma unroll
        for (int nj = 0; nj < 8; nj++) {
            const int c = bn + wn * 64 + nj * 8 + 2 * tig;
            if (MODE == 0) {
#pragma unroll
                for (int q = 0; q < 4; q++) {
                    const int row = (q < 2) ? r_top : r_bot;
                    const int col = c + (q & 1);
                    const int b = row >> 11;
                    const int n = row & 2047;
                    const int s = col % 3;
                    const int h = col / 192;
                    const int d = (col % 192) / 3;
                    const float val = f2tf32(acc[mi][nj][q] + bias[col]);
                    float* dst = (s == 0) ? g_q : (s == 1) ? g_k : g_v;
                    dst[(((size_t)(b * Hh + h)) * Nseq + n) * Dh + d] = val;
                }
            } else {
                const float2 bv = *(const float2*)(bias + c);
                float2 v0, v1;
                v0.x = acc[mi][nj][0] + bv.x; v0.y = acc[mi][nj][1] + bv.y;
                v1.x = acc[mi][nj][2] + bv.x; v1.y = acc[mi][nj][3] + bv.y;
                *(float2*)(out + (size_t)r_top * Emb + c) = v0;
                *(float2*)(out + (size_t)r_bot * Emb + c) = v1;
            }
        }
    }
}

// ---------------------------------------------------------------------------
// Flash attention, TF32 mma, register-resident online softmax.
// grid = (N/64, B*H), 128 threads = 4 warps. BR=64, BC=64, D=64.
// Tiles per block: qb+1 (vs 2qb+2 at BC=32) -> per-tile fixed costs halve.
// Double-buffered K/V smem, single __syncthreads per tile.
// Dynamic smem: 4224 (Q) + 2*4224 (K) + 2*4224 (V) + 4224 (S) = 25344 floats
//             = 101376 B. 2 CTAs/SM: 202752 B < 227 KB.
// ---------------------------------------------------------------------------
__global__ void __launch_bounds__(128, 2) flash_kernel()
{
    extern __shared__ float fsm[];
    float* Qs = fsm;            // A-chunks (m 0..3, kg 0..7): 4224
    float* Ks = fsm + 4224;     // 2 bufs x B-chunks (nb 0..7, kg 0..7): 4224 each
    float* Vs = fsm + 12672;    // 2 bufs x B-chunks (nb 0..7 [d], kg 0..7 [c]): 4224 each
    float* Ss = fsm + 21120;    // A-chunks per warp (4 warps x 8 x 132): 4224

    const int tid  = threadIdx.x;
    const int lane = tid & 31;
    const int w    = tid >> 5;
    const int gid  = lane >> 2;
    const int tig  = lane & 3;

    const int qb = (gridDim.x - 1) - blockIdx.x;   // heaviest blocks first
    const int bh = blockIdx.y;

    const float* Qg = g_q + ((size_t)bh * Nseq + qb * 64) * Dh;
    const float* Kg = g_k + (size_t)bh * Nseq * Dh;
    const float* Vg = g_v + (size_t)bh * Nseq * Dh;

    const float scale = 0.125f;   // exact on tf32 values (exponent-only)

    // Load & pre-scale Q tile (64x64) into A-chunk layout
#pragma unroll
    for (int i = 0; i < 8; i++) {
        const int idx = tid + i * 128;
        const int r = idx >> 4, c4 = (idx & 15) * 4;
        float4 q = *(const float4*)(Qg + r * Dh + c4);
        const int m = r >> 4, gidl = r & 7, half = (r >> 3) & 1;
        const int kg = c4 >> 3, kh = (c4 >> 2) & 1;
        float* qp = Qs + (m * 8 + kg) * 132 + half + 2 * kh;
        const float v[4] = {q.x * scale, q.y * scale, q.z * scale, q.w * scale};
#pragma unroll
        for (int u = 0; u < 4; u++) qp[(gidl * 4 + u) * 4] = v[u];
    }

    float m_top = -INFINITY, m_bot = -INFINITY;
    float l_top = 0.f, l_bot = 0.f;

    float oacc[8][4];
#pragma unroll
    for (int nj = 0; nj < 8; nj++)
#pragma unroll
        for (int q = 0; q < 4; q++) oacc[nj][q] = 0.f;

    float4 kS[8], vS[8];  // staging: 64x64 tile = 1024 float4 / 128 thr = 8 each
    auto ldg_kv = [&](int j) {
        const float* Kt = Kg + (size_t)j * 64 * Dh;
        const float* Vt = Vg + (size_t)j * 64 * Dh;
#pragma unroll
        for (int i = 0; i < 8; i++) {
            const int idx = tid + i * 128;
            const int r = idx >> 4, c4 = (idx & 15) * 4;
            kS[i] = *(const float4*)(Kt + r * Dh + c4);
            vS[i] = *(const float4*)(Vt + r * Dh + c4);
        }
    };

    const int ntiles = qb + 1;
    ldg_kv(0);
    for (int j = 0; j < ntiles; j++) {
        float* kb = Ks + (j & 1) * 4224;
        float* vb = Vs + (j & 1) * 4224;
        // store K/V tiles into B-chunk layouts (already tf32)
#pragma unroll
        for (int i = 0; i < 8; i++) {
            const int idx = tid + i * 128;
            const int r = idx >> 4, c4 = (idx & 15) * 4;
            {   // K: (seqrow r 0..63, col d 0..63) -> chunk(nb=r/8, kg=d/8)
                const int nb = r >> 3, gidb = r & 7;
                const int kg = c4 >> 3, kh = (c4 >> 2) & 1;
                float* kp = kb + (nb * 8 + kg) * 66 + kh;
                const float v[4] = {kS[i].x, kS[i].y, kS[i].z, kS[i].w};
#pragma unroll
                for (int u = 0; u < 4; u++) kp[(gidb * 4 + u) * 2] = v[u];
            }
            {   // V: (seqrow r = k-dim 0..63, col d = n-dim 0..63) -> chunk(nb=d/8, kg=r/8)
                const int nb = c4 >> 3;
                const int kg = r >> 3, kh = (r >> 2) & 1, tv = r & 3;
                float* vp = vb + (nb * 8 + kg) * 66 + kh;
                const float v[4] = {vS[i].x, vS[i].y, vS[i].z, vS[i].w};
#pragma unroll
                for (int u = 0; u < 4; u++)
                    vp[(((c4 & 7) + u) * 4 + tv) * 2] = v[u];
            }
        }
        __syncthreads();
        if (j + 1 < ntiles) ldg_kv(j + 1);

        // ---- S = Qs * Ks^T : warp rows w*16..+15, cols 0..63 ----
        float sacc[8][4];
#pragma unroll
        for (int nb = 0; nb < 8; nb++)
#pragma unroll
            for (int q = 0; q < 4; q++) sacc[nb][q] = 0.f;

#pragma unroll
        for (int kg = 0; kg < 8; kg++) {
            const float4 av = *(const float4*)(Qs + (w * 8 + kg) * 132 + lane * 4);
            unsigned af[4];
            af[0] = __float_as_uint(av.x); af[1] = __float_as_uint(av.y);
            af[2] = __float_as_uint(av.z); af[3] = __float_as_uint(av.w);
#pragma unroll
            for (int nb = 0; nb < 8; nb++) {
                const float2 bv = *(const float2*)(kb + (nb * 8 + kg) * 66 + lane * 2);
                unsigned bf[2];
                bf[0] = __float_as_uint(bv.x); bf[1] = __float_as_uint(bv.y);
                mma_tf32(sacc[nb], af, bf);
            }
        }

        // causal mask (only the diagonal tile j == qb)
        if (j == qb) {
            const int r0g = qb * 64 + w * 16 + gid;
            const int r1g = r0g + 8;
#pragma unroll
            for (int nb = 0; nb < 8; nb++) {
                const int cg = j * 64 + nb * 8 + 2 * tig;
                if (cg     > r0g) sacc[nb][0] = -INFINITY;
                if (cg + 1 > r0g) sacc[nb][1] = -INFINITY;
                if (cg     > r1g) sacc[nb][2] = -INFINITY;
                if (cg + 1 > r1g) sacc[nb][3] = -INFINITY;
            }
        }

        // ---- online softmax (quad shuffles) ----
        float mt_t = m_top, mt_b = m_bot;
#pragma unroll
        for (int nb = 0; nb < 8; nb++) {
            mt_t = fmaxf(mt_t, fmaxf(sacc[nb][0], sacc[nb][1]));
            mt_b = fmaxf(mt_b, fmaxf(sacc[nb][2], sacc[nb][3]));
        }
        mt_t = fmaxf(mt_t, __shfl_xor_sync(0xffffffffu, mt_t, 1));
        mt_t = fmaxf(mt_t, __shfl_xor_sync(0xffffffffu, mt_t, 2));
        mt_b = fmaxf(mt_b, __shfl_xor_sync(0xffffffffu, mt_b, 1));
        mt_b = fmaxf(mt_b, __shfl_xor_sync(0xffffffffu, mt_b, 2));

        const bool nochange = (mt_t == m_top) && (mt_b == m_bot);
        const float sc_t = nochange ? 1.f : __expf(m_top - mt_t);
        const float sc_b = nochange ? 1.f : __expf(m_bot - mt_b);
        float ps_t = 0.f, ps_b = 0.f;

        float* sbase = Ss + w * 8 * 132;
#pragma unroll
        for (int nb = 0; nb < 8; nb++) {
            float p[4];
            p[0] = __expf(sacc[nb][0] - mt_t);
            p[1] = __expf(sacc[nb][1] - mt_t);
            p[2] = __expf(sacc[nb][2] - mt_b);
            p[3] = __expf(sacc[nb][3] - mt_b);
            ps_t += p[0] + p[1];
            ps_b += p[2] + p[3];
#pragma unroll
            for (int q = 0; q < 4; q++) {
                const int par  = q & 1;
                const int half = q >> 1;
                const int kin  = 2 * tig + par;
                const int tigA = kin & 3;
                const int khA  = kin >> 2;
                sbase[nb * 132 + (gid * 4 + tigA) * 4 + half + 2 * khA] = f2tf32(p[q]);
            }
        }
        ps_t += __shfl_xor_sync(0xffffffffu, ps_t, 1);
        ps_t += __shfl_xor_sync(0xffffffffu, ps_t, 2);
        ps_b += __shfl_xor_sync(0xffffffffu, ps_b, 1);
        ps_b += __shfl_xor_sync(0xffffffffu, ps_b, 2);

        l_top = l_top * sc_t + ps_t;  m_top = mt_t;
        l_bot = l_bot * sc_b + ps_b;  m_bot = mt_b;

        __syncwarp();

        // ---- O = O*rescale + P*V (skip rescale when max unchanged warp-wide) ----
        if (!__all_sync(0xffffffffu, nochange)) {
#pragma unroll
            for (int nj = 0; nj < 8; nj++) {
                oacc[nj][0] *= sc_t; oacc[nj][1] *= sc_t;
                oacc[nj][2] *= sc_b; oacc[nj][3] *= sc_b;
            }
        }
#pragma unroll
        for (int kg = 0; kg < 8; kg++) {
            const float4 av = *(const float4*)(sbase + kg * 132 + lane * 4);
            unsigned af[4];
            af[0] = __float_as_uint(av.x); af[1] = __float_as_uint(av.y);
            af[2] = __float_as_uint(av.z); af[3] = __float_as_uint(av.w);
#pragma unroll
            for (int nb = 0; nb < 8; nb++) {
                const float2 bv = *(const float2*)(vb + (nb * 8 + kg) * 66 + lane * 2);
                unsigned bf[2];
                bf[0] = __float_as_uint(bv.x); bf[1] = __float_as_uint(bv.y);
                mma_tf32(oacc[nb], af, bf);
            }
        }
        // no end-of-loop sync: next iteration writes the other K/V buffer
    }

    const int b = bh >> 4, h = bh & 15;
    const float inv_top = 1.f / l_top;
    const float inv_bot = 1.f / l_bot;
    const int n_top = qb * 64 + w * 16 + gid;
    const int n_bot = n_top + 8;
#pragma unroll
    for (int nj = 0; nj < 8; nj++) {
        const int c = nj * 8 + 2 * tig;
        float2 v0, v1;
        v0.x = f2tf32(oacc[nj][0] * inv_top); v0.y = f2tf32(oacc[nj][1] * inv_top);
        v1.x = f2tf32(oacc[nj][2] * inv_bot); v1.y = f2tf32(oacc[nj][3] * inv_bot);
        *(float2*)(g_ao + ((size_t)(b * Nseq + n_top)) * (Hh * Dh) + h * Dh + c) = v0;
        *(float2*)(g_ao + ((size_t)(b * Nseq + n_bot)) * (Hh * Dh) + h * Dh + c) = v1;
    }
}

// ---------------------------------------------------------------------------
extern "C" void kernel_launch(void* const* d_in, const int* in_sizes, int n_in,
                              void* d_out, int out_size)
{
    const float* x    = (const float*)d_in[0];
    const float* Wqkv = (const float*)d_in[1];
    const float* bqkv = (const float*)d_in[2];
    const float* Wout = (const float*)d_in[3];
    const float* bout = (const float*)d_in[4];
    float* out = (float*)d_out;

    // raise dynamic smem limits (idempotent)
    cudaFuncSetAttribute(gemm_tf32_kernel<0>, cudaFuncAttributeMaxDynamicSharedMemorySize, 65536);
    cudaFuncSetAttribute(gemm_tf32_kernel<1>, cudaFuncAttributeMaxDynamicSharedMemorySize, 65536);
    cudaFuncSetAttribute(flash_kernel, cudaFuncAttributeMaxDynamicSharedMemorySize, 101376);

    float *gx, *gwq, *gwo;
    cudaGetSymbolAddress((void**)&gx,  g_x);
    cudaGetSymbolAddress((void**)&gwq, g_wq);
    cudaGetSymbolAddress((void**)&gwo, g_wo);

    // K0: tf32 pre-conversion (single launch)
    const int n1 = Bsz * Nseq * Emb / 4;
    const int n2 = 3 * Hh * Dh * Emb / 4;
    const int n3 = Emb * Hh * Dh / 4;
    cvt_tf32_kernel<<<(n1 + n2 + n3 + 255) / 256, 256>>>(
        (const float4*)x, (float4*)gx, n1,
        (const float4*)Wqkv, (float4*)gwq, n2,
        (const float4*)Wout, (float4*)gwo, n3);

    // K1: QKV projection + de-interleave scatter. C is [4096, 3072].
    gemm_tf32_kernel<0><<<dim3(3072 / 128, 4096 / 128), 256, 65536>>>(bqkv, nullptr);

    // K2: causal flash attention. grid (N/64, B*H).
    flash_kernel<<<dim3(Nseq / 64, Bsz * Hh), 128, 101376>>>();

    // K3: output projection. C is [4096, 1024].
    gemm_tf32_kernel<1><<<dim3(1024 / 128, 4096 / 128), 256, 65536>>>(bout, out);
}

// round 13
// speedup vs baseline: 1.0554x; 1.0554x over previous
#include <cuda_runtime.h>
#include <math.h>

#define Bsz  2
#define Nseq 2048
#define Emb  1024
#define Hh   16
#define Dh   64

// Scratch (allocation-free: __device__ globals)
__device__ float g_q [Bsz * Hh * Nseq * Dh];   // [B,H,N,D] (tf32-rounded)
__device__ float g_k [Bsz * Hh * Nseq * Dh];
__device__ float g_v [Bsz * Hh * Nseq * Dh];
__device__ float g_ao[Bsz * Nseq * Hh * Dh];   // [B,N,H*D] (tf32-rounded)
__device__ float g_x [Bsz * Nseq * Emb];       // tf32-rounded x
__device__ float g_wq[3 * Hh * Dh * Emb];      // tf32-rounded Wqkv
__device__ float g_wo[Emb * Hh * Dh];          // tf32-rounded Wout

// ---------------------------------------------------------------------------
// helpers
// ---------------------------------------------------------------------------
__device__ __forceinline__ float f2tf32(float f) {
    unsigned r;
    asm("cvt.rna.tf32.f32 %0, %1;" : "=r"(r) : "f"(f));
    return __uint_as_float(r);
}

__device__ __forceinline__ void mma_tf32(float* c, const unsigned* a, const unsigned* b) {
    asm volatile(
        "mma.sync.aligned.m16n8k8.row.col.f32.tf32.tf32.f32 "
        "{%0,%1,%2,%3},{%4,%5,%6,%7},{%8,%9},{%0,%1,%2,%3};"
        : "+f"(c[0]), "+f"(c[1]), "+f"(c[2]), "+f"(c[3])
        : "r"(a[0]), "r"(a[1]), "r"(a[2]), "r"(a[3]), "r"(b[0]), "r"(b[1]));
}

__device__ __forceinline__ void ldsm_x4(unsigned& r0, unsigned& r1, unsigned& r2, unsigned& r3,
                                        unsigned saddr) {
    asm volatile("ldmatrix.sync.aligned.m8n8.x4.shared.b16 {%0,%1,%2,%3}, [%4];"
                 : "=r"(r0), "=r"(r1), "=r"(r2), "=r"(r3) : "r"(saddr));
}

__device__ __forceinline__ void cp16(void* dst_smem, const void* src_gmem) {
    unsigned d = (unsigned)__cvta_generic_to_shared(dst_smem);
    asm volatile("cp.async.cg.shared.global [%0], [%1], 16;" :: "r"(d), "l"(src_gmem));
}

// ---------------------------------------------------------------------------
// tf32 pre-convert pass (all three tensors in one launch)
// ---------------------------------------------------------------------------
__global__ void cvt_tf32_kernel(const float4* __restrict__ x_in,  float4* __restrict__ x_out,  int n1,
                                const float4* __restrict__ wq_in, float4* __restrict__ wq_out, int n2,
                                const float4* __restrict__ wo_in, float4* __restrict__ wo_out, int n3)
{
    const int i = blockIdx.x * 256 + threadIdx.x;
    const float4* src; float4* dst; int idx;
    if (i < n1)            { src = x_in;  dst = x_out;  idx = i; }
    else if (i < n1 + n2)  { src = wq_in; dst = wq_out; idx = i - n1; }
    else if (i < n1 + n2 + n3) { src = wo_in; dst = wo_out; idx = i - n1 - n2; }
    else return;
    float4 v = src[idx];
    float4 r;
    r.x = f2tf32(v.x); r.y = f2tf32(v.y); r.z = f2tf32(v.z); r.w = f2tf32(v.w);
    dst[idx] = r;
}

// ---------------------------------------------------------------------------
// TF32 GEMM (R5 version — best measured: K1=188.4us, K3=55.3us).
// 128x128 block tile, BK=32, 256 threads = 8 warps (4 x 2), warp tile 32x64.
// cp.async 2-stage pipeline, 128B-swizzled smem, ldmatrix fragment loads.
// Dynamic smem: 2*(128*32)*2 floats = 64 KB.
// ---------------------------------------------------------------------------
template <int MODE>
__global__ void __launch_bounds__(256, 2) gemm_tf32_kernel(const float* __restrict__ bias,
                                                           float* __restrict__ out)
{
    extern __shared__ float smem[];
    float* Asm = smem;          // 2 stages x 4096 floats
    float* Wsm = smem + 8192;   // 2 stages x 4096 floats

    const float* Ain = (MODE == 0) ? g_x  : g_ao;
    const float* Win = (MODE == 0) ? g_wq : g_wo;

    const int tid  = threadIdx.x;
    const int lane = tid & 31;
    const int warp = tid >> 5;
    const int wm   = warp & 3;         // 0..3 : 32-row group
    const int wn   = warp >> 2;        // 0..1 : 64-col group
    const int bm = blockIdx.y * 128;
    const int bn = blockIdx.x * 128;

    const int gid = lane >> 2;
    const int tig = lane & 3;

    // ldmatrix per-lane address components
    const int a_row  = lane & 15;
    const int a_cbit = lane >> 4;
    const int b_row  = (lane & 7) + ((lane & 16) >> 1);
    const int b_cbit = (lane >> 3) & 1;

    float acc[2][8][4];
#pragma unroll
    for (int mi = 0; mi < 2; mi++)
#pragma unroll
        for (int nj = 0; nj < 8; nj++)
#pragma unroll
            for (int q = 0; q < 4; q++) acc[mi][nj][q] = 0.f;

    auto cp_tile = [&](int kt, int stage) {
        const float* Ab = Ain + (size_t)bm * Emb + kt * 32;
        const float* Wb = Win + (size_t)bn * Emb + kt * 32;
        float* as = Asm + stage * 4096;
        float* ws = Wsm + stage * 4096;
#pragma unroll
        for (int i = 0; i < 4; i++) {
            const int idx = tid + i * 256;          // 0..1023
            const int row = idx >> 3;               // 0..127
            const int ch  = idx & 7;                // 16B chunk
            const int off = row * 32 + ((ch ^ (row & 7)) << 2);
            cp16(as + off, Ab + (size_t)row * Emb + ch * 4);
            cp16(ws + off, Wb + (size_t)row * Emb + ch * 4);
        }
        asm volatile("cp.async.commit_group;");
    };

    const int NT = Emb / 32;
    cp_tile(0, 0);

    for (int kt = 0; kt < NT; kt++) {
        if (kt + 1 < NT) {
            cp_tile(kt + 1, (kt + 1) & 1);
            asm volatile("cp.async.wait_group 1;");
        } else {
            asm volatile("cp.async.wait_group 0;");
        }
        __syncthreads();

        const float* as = Asm + (kt & 1) * 4096;
        const float* ws = Wsm + (kt & 1) * 4096;

#pragma unroll
        for (int kk8 = 0; kk8 < 4; kk8++) {
            unsigned afrag[2][4];
#pragma unroll
            for (int mi = 0; mi < 2; mi++) {
                const int row = wm * 32 + mi * 16 + a_row;
                const int ch  = kk8 * 2 + a_cbit;
                const unsigned sa = (unsigned)__cvta_generic_to_shared(
                    as + row * 32 + ((ch ^ (row & 7)) << 2));
                ldsm_x4(afrag[mi][0], afrag[mi][1], afrag[mi][2], afrag[mi][3], sa);
            }
            unsigned bfrag[8][2];
#pragma unroll
            for (int nj2 = 0; nj2 < 4; nj2++) {
                const int row = wn * 64 + nj2 * 16 + b_row;
                const int ch  = kk8 * 2 + b_cbit;
                const unsigned sb = (unsigned)__cvta_generic_to_shared(
                    ws + row * 32 + ((ch ^ (row & 7)) << 2));
                ldsm_x4(bfrag[nj2 * 2][0], bfrag[nj2 * 2][1],
                        bfrag[nj2 * 2 + 1][0], bfrag[nj2 * 2 + 1][1], sb);
            }
#pragma unroll
            for (int mi = 0; mi < 2; mi++)
#pragma unroll
                for (int nj = 0; nj < 8; nj++)
                    mma_tf32(acc[mi][nj], afrag[mi], bfrag[nj]);
        }
        __syncthreads();
    }

    // epilogue
#pragma unroll
    for (int mi = 0; mi < 2; mi++) {
        const int r_top = bm + wm * 32 + mi * 16 + gid;
        const int r_bot = r_top + 8;
#pragma unroll
        for (int nj = 0; nj < 8; nj++) {
            const int c = bn + wn * 64 + nj * 8 + 2 * tig;
            if (MODE == 0) {
#pragma unroll
                for (int q = 0; q < 4; q++) {
                    const int row = (q < 2) ? r_top : r_bot;
                    const int col = c + (q & 1);
                    const int b = row >> 11;
                    const int n = row & 2047;
                    const int s = col % 3;
                    const int h = col / 192;
                    const int d = (col % 192) / 3;
                    const float val = f2tf32(acc[mi][nj][q] + bias[col]);
                    float* dst = (s == 0) ? g_q : (s == 1) ? g_k : g_v;
                    dst[(((size_t)(b * Hh + h)) * Nseq + n) * Dh + d] = val;
                }
            } else {
                const float2 bv = *(const float2*)(bias + c);
                float2 v0, v1;
                v0.x = acc[mi][nj][0] + bv.x; v0.y = acc[mi][nj][1] + bv.y;
                v1.x = acc[mi][nj][2] + bv.x; v1.y = acc[mi][nj][3] + bv.y;
                *(float2*)(out + (size_t)r_top * Emb + c) = v0;
                *(float2*)(out + (size_t)r_bot * Emb + c) = v1;
            }
        }
    }
}

// ---------------------------------------------------------------------------
// Flash attention (R5 version — best measured ≈225us). TF32 mma,
// register-resident online softmax. grid = (N/64, B*H), 128 threads = 4 warps.
// BR=64, BC=32. Double-buffered K/V smem, single __syncthreads per tile.
// Dynamic smem: (4224 + 2*2112 + 2*2112 + 2112) floats = 59136 B.
// ---------------------------------------------------------------------------
__global__ void __launch_bounds__(128, 2) flash_kernel()
{
    extern __shared__ float fsm[];
    float* Qs = fsm;            // A-chunks (m 0..3, kg 0..7): 4224
    float* Ks = fsm + 4224;     // 2 bufs x B-chunks (nb 0..3, kg 0..7): 2112 each
    float* Vs = fsm + 8448;     // 2 bufs x B-chunks (nb 0..7, kg 0..3): 2112 each
    float* Ss = fsm + 12672;    // A-chunks per warp: 2112

    const int tid  = threadIdx.x;
    const int lane = tid & 31;
    const int w    = tid >> 5;
    const int gid  = lane >> 2;
    const int tig  = lane & 3;

    const int qb = (gridDim.x - 1) - blockIdx.x;   // heaviest blocks first
    const int bh = blockIdx.y;

    const float* Qg = g_q + ((size_t)bh * Nseq + qb * 64) * Dh;
    const float* Kg = g_k + (size_t)bh * Nseq * Dh;
    const float* Vg = g_v + (size_t)bh * Nseq * Dh;

    const float scale = 0.125f;   // exact on tf32 values (exponent-only)

    // Load & pre-scale Q tile (64x64) into A-chunk layout
#pragma unroll
    for (int i = 0; i < 8; i++) {
        const int idx = tid + i * 128;
        const int r = idx >> 4, c4 = (idx & 15) * 4;
        float4 q = *(const float4*)(Qg + r * Dh + c4);
        const int m = r >> 4, gidl = r & 7, half = (r >> 3) & 1;
        const int kg = c4 >> 3, kh = (c4 >> 2) & 1;
        float* qp = Qs + (m * 8 + kg) * 132 + half + 2 * kh;
        const float v[4] = {q.x * scale, q.y * scale, q.z * scale, q.w * scale};
#pragma unroll
        for (int u = 0; u < 4; u++) qp[(gidl * 4 + u) * 4] = v[u];
    }

    float m_top = -INFINITY, m_bot = -INFINITY;
    float l_top = 0.f, l_bot = 0.f;

    float oacc[8][4];
#pragma unroll
    for (int nj = 0; nj < 8; nj++)
#pragma unroll
        for (int q = 0; q < 4; q++) oacc[nj][q] = 0.f;

    float4 kS[4], vS[4];  // staging
    auto ldg_kv = [&](int j) {
        const float* Kt = Kg + (size_t)j * 32 * Dh;
        const float* Vt = Vg + (size_t)j * 32 * Dh;
#pragma unroll
        for (int i = 0; i < 4; i++) {
            const int idx = tid + i * 128;
            const int r = idx >> 4, c4 = (idx & 15) * 4;
            kS[i] = *(const float4*)(Kt + r * Dh + c4);
            vS[i] = *(const float4*)(Vt + r * Dh + c4);
        }
    };

    const int ntiles = 2 * qb + 2;
    ldg_kv(0);
    for (int j = 0; j < ntiles; j++) {
        float* kb = Ks + (j & 1) * 2112;
        float* vb = Vs + (j & 1) * 2112;
        // store K/V tiles into B-chunk layouts (already tf32)
#pragma unroll
        for (int i = 0; i < 4; i++) {
            const int idx = tid + i * 128;
            const int r = idx >> 4, c4 = (idx & 15) * 4;
            {   // K: (seqrow r, col d) -> chunk(nb=r/8, kg=d/8)
                const int nb = r >> 3, gidb = r & 7;
                const int kg = c4 >> 3, kh = (c4 >> 2) & 1;
                float* kp = kb + (nb * 8 + kg) * 66 + kh;
                const float v[4] = {kS[i].x, kS[i].y, kS[i].z, kS[i].w};
#pragma unroll
                for (int u = 0; u < 4; u++) kp[(gidb * 4 + u) * 2] = v[u];
            }
            {   // V: (seqrow r = k-dim, col d = n-dim) -> chunk(nb=d/8, kg=r/8)
                const int nb = c4 >> 3;
                const int kg = r >> 3, kh = (r >> 2) & 1, tv = r & 3;
                float* vp = vb + (nb * 4 + kg) * 66 + kh;
                const float v[4] = {vS[i].x, vS[i].y, vS[i].z, vS[i].w};
#pragma unroll
                for (int u = 0; u < 4; u++)
                    vp[(((c4 & 7) + u) * 4 + tv) * 2] = v[u];
            }
        }
        __syncthreads();
        if (j + 1 < ntiles) ldg_kv(j + 1);

        // ---- S = Qs * Ks^T ----
        float sacc[4][4];
#pragma unroll
        for (int nb = 0; nb < 4; nb++)
#pragma unroll
            for (int q = 0; q < 4; q++) sacc[nb][q] = 0.f;

#pragma unroll
        for (int kg = 0; kg < 8; kg++) {
            const float4 av = *(const float4*)(Qs + (w * 8 + kg) * 132 + lane * 4);
            unsigned af[4];
            af[0] = __float_as_uint(av.x); af[1] = __float_as_uint(av.y);
            af[2] = __float_as_uint(av.z); af[3] = __float_as_uint(av.w);
#pragma unroll
            for (int nb = 0; nb < 4; nb++) {
                const float2 bv = *(const float2*)(kb + (nb * 8 + kg) * 66 + lane * 2);
                unsigned bf[2];
                bf[0] = __float_as_uint(bv.x); bf[1] = __float_as_uint(bv.y);
                mma_tf32(sacc[nb], af, bf);
            }
        }

        // causal mask
        if (j >= 2 * qb) {
            const int r0g = qb * 64 + w * 16 + gid;
            const int r1g = r0g + 8;
#pragma unroll
            for (int nb = 0; nb < 4; nb++) {
                const int cg = j * 32 + nb * 8 + 2 * tig;
                if (cg     > r0g) sacc[nb][0] = -INFINITY;
                if (cg + 1 > r0g) sacc[nb][1] = -INFINITY;
                if (cg     > r1g) sacc[nb][2] = -INFINITY;
                if (cg + 1 > r1g) sacc[nb][3] = -INFINITY;
            }
        }

        // ---- online softmax (quad shuffles) ----
        float mt_t = m_top, mt_b = m_bot;
#pragma unroll
        for (int nb = 0; nb < 4; nb++) {
            mt_t = fmaxf(mt_t, fmaxf(sacc[nb][0], sacc[nb][1]));
            mt_b = fmaxf(mt_b, fmaxf(sacc[nb][2], sacc[nb][3]));
        }
        mt_t = fmaxf(mt_t, __shfl_xor_sync(0xffffffffu, mt_t, 1));
        mt_t = fmaxf(mt_t, __shfl_xor_sync(0xffffffffu, mt_t, 2));
        mt_b = fmaxf(mt_b, __shfl_xor_sync(0xffffffffu, mt_b, 1));
        mt_b = fmaxf(mt_b, __shfl_xor_sync(0xffffffffu, mt_b, 2));

        const bool nochange = (mt_t == m_top) && (mt_b == m_bot);
        const float sc_t = nochange ? 1.f : __expf(m_top - mt_t);
        const float sc_b = nochange ? 1.f : __expf(m_bot - mt_b);
        float ps_t = 0.f, ps_b = 0.f;

        float* sbase = Ss + w * 4 * 132;
#pragma unroll
        for (int nb = 0; nb < 4; nb++) {
            float p[4];
            p[0] = __expf(sacc[nb][0] - mt_t);
            p[1] = __expf(sacc[nb][1] - mt_t);
            p[2] = __expf(sacc[nb][2] - mt_b);
            p[3] = __expf(sacc[nb][3] - mt_b);
            ps_t += p[0] + p[1];
            ps_b += p[2] + p[3];
#pragma unroll
            for (int q = 0; q < 4; q++) {
                const int par  = q & 1;
                const int half = q >> 1;
                const int kin  = 2 * tig + par;
                const int tigA = kin & 3;
                const int khA  = kin >> 2;
                sbase[nb * 132 + (gid * 4 + tigA) * 4 + half + 2 * khA] = f2tf32(p[q]);
            }
        }
        ps_t += __shfl_xor_sync(0xffffffffu, ps_t, 1);
        ps_t += __shfl_xor_sync(0xffffffffu, ps_t, 2);
        ps_b += __shfl_xor_sync(0xffffffffu, ps_b, 1);
        ps_b += __shfl_xor_sync(0xffffffffu, ps_b, 2);

        l_top = l_top * sc_t + ps_t;  m_top = mt_t;
        l_bot = l_bot * sc_b + ps_b;  m_bot = mt_b;

        __syncwarp();

        // ---- O = O*rescale + P*V (skip rescale when max unchanged warp-wide) ----
        if (!__all_sync(0xffffffffu, nochange)) {
#pragma unroll
            for (int nj = 0; nj < 8; nj++) {
                oacc[nj][0] *= sc_t; oacc[nj][1] *= sc_t;
                oacc[nj][2] *= sc_b; oacc[nj][3] *= sc_b;
            }
        }
#pragma unroll
        for (int kg = 0; kg < 4; kg++) {
            const float4 av = *(const float4*)(sbase + kg * 132 + lane * 4);
            unsigned af[4];
            af[0] = __float_as_uint(av.x); af[1] = __float_as_uint(av.y);
            af[2] = __float_as_uint(av.z); af[3] = __float_as_uint(av.w);
#pragma unroll
            for (int nb = 0; nb < 8; nb++) {
                const float2 bv = *(const float2*)(vb + (nb * 4 + kg) * 66 + lane * 2);
                unsigned bf[2];
                bf[0] = __float_as_uint(bv.x); bf[1] = __float_as_uint(bv.y);
                mma_tf32(oacc[nb], af, bf);
            }
        }
        // no end-of-loop sync: next iteration writes the other K/V buffer
    }

    const int b = bh >> 4, h = bh & 15;
    const float inv_top = 1.f / l_top;
    const float inv_bot = 1.f / l_bot;
    const int n_top = qb * 64 + w * 16 + gid;
    const int n_bot = n_top + 8;
#pragma unroll
    for (int nj = 0; nj < 8; nj++) {
        const int c = nj * 8 + 2 * tig;
        float2 v0, v1;
        v0.x = f2tf32(oacc[nj][0] * inv_top); v0.y = f2tf32(oacc[nj][1] * inv_top);
        v1.x = f2tf32(oacc[nj][2] * inv_bot); v1.y = f2tf32(oacc[nj][3] * inv_bot);
        *(float2*)(g_ao + ((size_t)(b * Nseq + n_top)) * (Hh * Dh) + h * Dh + c) = v0;
        *(float2*)(g_ao + ((size_t)(b * Nseq + n_bot)) * (Hh * Dh) + h * Dh + c) = v1;
    }
}

// ---------------------------------------------------------------------------
extern "C" void kernel_launch(void* const* d_in, const int* in_sizes, int n_in,
                              void* d_out, int out_size)
{
    const float* x    = (const float*)d_in[0];
    const float* Wqkv = (const float*)d_in[1];
    const float* bqkv = (const float*)d_in[2];
    const float* Wout = (const float*)d_in[3];
    const float* bout = (const float*)d_in[4];
    float* out = (float*)d_out;

    // raise dynamic smem limits (idempotent)
    cudaFuncSetAttribute(gemm_tf32_kernel<0>, cudaFuncAttributeMaxDynamicSharedMemorySize, 65536);
    cudaFuncSetAttribute(gemm_tf32_kernel<1>, cudaFuncAttributeMaxDynamicSharedMemorySize, 65536);
    cudaFuncSetAttribute(flash_kernel, cudaFuncAttributeMaxDynamicSharedMemorySize, 59136);

    float *gx, *gwq, *gwo;
    cudaGetSymbolAddress((void**)&gx,  g_x);
    cudaGetSymbolAddress((void**)&gwq, g_wq);
    cudaGetSymbolAddress((void**)&gwo, g_wo);

    // K0: tf32 pre-conversion (single launch)
    const int n1 = Bsz * Nseq * Emb / 4;
    const int n2 = 3 * Hh * Dh * Emb / 4;
    const int n3 = Emb * Hh * Dh / 4;
    cvt_tf32_kernel<<<(n1 + n2 + n3 + 255) / 256, 256>>>(
        (const float4*)x, (float4*)gx, n1,
        (const float4*)Wqkv, (float4*)gwq, n2,
        (const float4*)Wout, (float4*)gwo, n3);

    // K1: QKV projection + de-interleave scatter. C is [4096, 3072].
    gemm_tf32_kernel<0><<<dim3(3072 / 128, 4096 / 128), 256, 65536>>>(bqkv, nullptr);

    // K2: causal flash attention. grid (N/64, B*H).
    flash_kernel<<<dim3(Nseq / 64, Bsz * Hh), 128, 59136>>>();

    // K3: output projection. C is [4096, 1024].
    gemm_tf32_kernel<1><<<dim3(1024 / 128, 4096 / 128), 256, 65536>>>(bout, out);
}

// round 14
// speedup vs baseline: 1.1255x; 1.0664x over previous
#include <cuda_runtime.h>
#include <math.h>

#define Bsz  2
#define Nseq 2048
#define Emb  1024
#define Hh   16
#define Dh   64

// Scratch (allocation-free: __device__ globals)
__device__ float g_q [Bsz * Hh * Nseq * Dh];   // [B,H,N,D] (tf32-rounded)
__device__ float g_k [Bsz * Hh * Nseq * Dh];
__device__ float g_v [Bsz * Hh * Nseq * Dh];
__device__ float g_ao[Bsz * Nseq * Hh * Dh];   // [B,N,H*D] (tf32-rounded)
__device__ float g_x [Bsz * Nseq * Emb];       // tf32-rounded x
__device__ float g_wq[3 * Hh * Dh * Emb];      // tf32-rounded Wqkv
__device__ float g_wo[Emb * Hh * Dh];          // tf32-rounded Wout

// ---------------------------------------------------------------------------
// helpers
// ---------------------------------------------------------------------------
__device__ __forceinline__ float f2tf32(float f) {
    unsigned r;
    asm("cvt.rna.tf32.f32 %0, %1;" : "=r"(r) : "f"(f));
    return __uint_as_float(r);
}

__device__ __forceinline__ void mma_tf32(float* c, const unsigned* a, const unsigned* b) {
    asm volatile(
        "mma.sync.aligned.m16n8k8.row.col.f32.tf32.tf32.f32 "
        "{%0,%1,%2,%3},{%4,%5,%6,%7},{%8,%9},{%0,%1,%2,%3};"
        : "+f"(c[0]), "+f"(c[1]), "+f"(c[2]), "+f"(c[3])
        : "r"(a[0]), "r"(a[1]), "r"(a[2]), "r"(a[3]), "r"(b[0]), "r"(b[1]));
}

__device__ __forceinline__ void ldsm_x4(unsigned& r0, unsigned& r1, unsigned& r2, unsigned& r3,
                                        unsigned saddr) {
    asm volatile("ldmatrix.sync.aligned.m8n8.x4.shared.b16 {%0,%1,%2,%3}, [%4];"
                 : "=r"(r0), "=r"(r1), "=r"(r2), "=r"(r3) : "r"(saddr));
}

__device__ __forceinline__ void cp16(void* dst_smem, const void* src_gmem) {
    unsigned d = (unsigned)__cvta_generic_to_shared(dst_smem);
    asm volatile("cp.async.cg.shared.global [%0], [%1], 16;" :: "r"(d), "l"(src_gmem));
}

// ---------------------------------------------------------------------------
// tf32 pre-convert pass (all three tensors in one launch)
// ---------------------------------------------------------------------------
__global__ void cvt_tf32_kernel(const float4* __restrict__ x_in,  float4* __restrict__ x_out,  int n1,
                                const float4* __restrict__ wq_in, float4* __restrict__ wq_out, int n2,
                                const float4* __restrict__ wo_in, float4* __restrict__ wo_out, int n3)
{
    const int i = blockIdx.x * 256 + threadIdx.x;
    const float4* src; float4* dst; int idx;
    if (i < n1)            { src = x_in;  dst = x_out;  idx = i; }
    else if (i < n1 + n2)  { src = wq_in; dst = wq_out; idx = i - n1; }
    else if (i < n1 + n2 + n3) { src = wo_in; dst = wo_out; idx = i - n1 - n2; }
    else return;
    float4 v = src[idx];
    float4 r;
    r.x = f2tf32(v.x); r.y = f2tf32(v.y); r.z = f2tf32(v.z); r.w = f2tf32(v.w);
    dst[idx] = r;
}

// ---------------------------------------------------------------------------
// TF32 GEMM (R5 version — best measured: K1=188.4us, K3=55.3us). UNCHANGED.
// 128x128 block tile, BK=32, 256 threads = 8 warps (4 x 2), warp tile 32x64.
// cp.async 2-stage pipeline, 128B-swizzled smem, ldmatrix fragment loads.
// Dynamic smem: 2*(128*32)*2 floats = 64 KB.
// ---------------------------------------------------------------------------
template <int MODE>
__global__ void __launch_bounds__(256, 2) gemm_tf32_kernel(const float* __restrict__ bias,
                                                           float* __restrict__ out)
{
    extern __shared__ float smem[];
    float* Asm = smem;          // 2 stages x 4096 floats
    float* Wsm = smem + 8192;   // 2 stages x 4096 floats

    const float* Ain = (MODE == 0) ? g_x  : g_ao;
    const float* Win = (MODE == 0) ? g_wq : g_wo;

    const int tid  = threadIdx.x;
    const int lane = tid & 31;
    const int warp = tid >> 5;
    const int wm   = warp & 3;         // 0..3 : 32-row group
    const int wn   = warp >> 2;        // 0..1 : 64-col group
    const int bm = blockIdx.y * 128;
    const int bn = blockIdx.x * 128;

    const int gid = lane >> 2;
    const int tig = lane & 3;

    // ldmatrix per-lane address components
    const int a_row  = lane & 15;
    const int a_cbit = lane >> 4;
    const int b_row  = (lane & 7) + ((lane & 16) >> 1);
    const int b_cbit = (lane >> 3) & 1;

    float acc[2][8][4];
#pragma unroll
    for (int mi = 0; mi < 2; mi++)
#pragma unroll
        for (int nj = 0; nj < 8; nj++)
#pragma unroll
            for (int q = 0; q < 4; q++) acc[mi][nj][q] = 0.f;

    auto cp_tile = [&](int kt, int stage) {
        const float* Ab = Ain + (size_t)bm * Emb + kt * 32;
        const float* Wb = Win + (size_t)bn * Emb + kt * 32;
        float* as = Asm + stage * 4096;
        float* ws = Wsm + stage * 4096;
#pragma unroll
        for (int i = 0; i < 4; i++) {
            const int idx = tid + i * 256;          // 0..1023
            const int row = idx >> 3;               // 0..127
            const int ch  = idx & 7;                // 16B chunk
            const int off = row * 32 + ((ch ^ (row & 7)) << 2);
            cp16(as + off, Ab + (size_t)row * Emb + ch * 4);
            cp16(ws + off, Wb + (size_t)row * Emb + ch * 4);
        }
        asm volatile("cp.async.commit_group;");
    };

    const int NT = Emb / 32;
    cp_tile(0, 0);

    for (int kt = 0; kt < NT; kt++) {
        if (kt + 1 < NT) {
            cp_tile(kt + 1, (kt + 1) & 1);
            asm volatile("cp.async.wait_group 1;");
        } else {
            asm volatile("cp.async.wait_group 0;");
        }
        __syncthreads();

        const float* as = Asm + (kt & 1) * 4096;
        const float* ws = Wsm + (kt & 1) * 4096;

#pragma unroll
        for (int kk8 = 0; kk8 < 4; kk8++) {
            unsigned afrag[2][4];
#pragma unroll
            for (int mi = 0; mi < 2; mi++) {
                const int row = wm * 32 + mi * 16 + a_row;
                const int ch  = kk8 * 2 + a_cbit;
                const unsigned sa = (unsigned)__cvta_generic_to_shared(
                    as + row * 32 + ((ch ^ (row & 7)) << 2));
                ldsm_x4(afrag[mi][0], afrag[mi][1], afrag[mi][2], afrag[mi][3], sa);
            }
            unsigned bfrag[8][2];
#pragma unroll
            for (int nj2 = 0; nj2 < 4; nj2++) {
                const int row = wn * 64 + nj2 * 16 + b_row;
                const int ch  = kk8 * 2 + b_cbit;
                const unsigned sb = (unsigned)__cvta_generic_to_shared(
                    ws + row * 32 + ((ch ^ (row & 7)) << 2));
                ldsm_x4(bfrag[nj2 * 2][0], bfrag[nj2 * 2][1],
                        bfrag[nj2 * 2 + 1][0], bfrag[nj2 * 2 + 1][1], sb);
            }
#pragma unroll
            for (int mi = 0; mi < 2; mi++)
#pragma unroll
                for (int nj = 0; nj < 8; nj++)
                    mma_tf32(acc[mi][nj], afrag[mi], bfrag[nj]);
        }
        __syncthreads();
    }

    // epilogue
#pragma unroll
    for (int mi = 0; mi < 2; mi++) {
        const int r_top = bm + wm * 32 + mi * 16 + gid;
        const int r_bot = r_top + 8;
#pragma unroll
        for (int nj = 0; nj < 8; nj++) {
            const int c = bn + wn * 64 + nj * 8 + 2 * tig;
            if (MODE == 0) {
#pragma unroll
                for (int q = 0; q < 4; q++) {
                    const int row = (q < 2) ? r_top : r_bot;
                    const int col = c + (q & 1);
                    const int b = row >> 11;
                    const int n = row & 2047;
                    const int s = col % 3;
                    const int h = col / 192;
                    const int d = (col % 192) / 3;
                    const float val = f2tf32(acc[mi][nj][q] + bias[col]);
                    float* dst = (s == 0) ? g_q : (s == 1) ? g_k : g_v;
                    dst[(((size_t)(b * Hh + h)) * Nseq + n) * Dh + d] = val;
                }
            } else {
                const float2 bv = *(const float2*)(bias + c);
                float2 v0, v1;
                v0.x = acc[mi][nj][0] + bv.x; v0.y = acc[mi][nj][1] + bv.y;
                v1.x = acc[mi][nj][2] + bv.x; v1.y = acc[mi][nj][3] + bv.y;
                *(float2*)(out + (size_t)r_top * Emb + c) = v0;
                *(float2*)(out + (size_t)r_bot * Emb + c) = v1;
            }
        }
    }
}

// ---------------------------------------------------------------------------
// Flash attention v2: K-path via cp.async + swizzled subtiles + ldmatrix
// (same mechanism that won R4->R5 in the GEMM). Q/P/V paths unchanged (R5).
// grid = (N/64, B*H), 128 threads = 4 warps. BR=64, BC=32.
// K tile layout: 2 subtiles [32 seq-rows x 32 floats(128B)] with GEMM swizzle,
// subtile s holds d = s*32..s*32+31. Double buffered (2 x 2048 floats).
// Dynamic smem: 4224 (Qs) + 4096 (Ks) + 2*2112 (Vs) + 2112 (Ss)
//             = 14656 floats = 58624 B. 2 CTAs/SM.
// ---------------------------------------------------------------------------
__global__ void __launch_bounds__(128, 2) flash_kernel()
{
    extern __shared__ float fsm[];
    float* Qs = fsm;            // A-chunks (m 0..3, kg 0..7): 4224
    float* Ks = fsm + 4224;     // 2 bufs x swizzled K subtiles: 2048 each
    float* Vs = fsm + 8320;     // 2 bufs x B-chunks (nb 0..7, kg 0..3): 2112 each
    float* Ss = fsm + 12544;    // A-chunks per warp: 2112

    const int tid  = threadIdx.x;
    const int lane = tid & 31;
    const int w    = tid >> 5;
    const int gid  = lane >> 2;
    const int tig  = lane & 3;

    // ldmatrix B per-lane address components (same as GEMM)
    const int b_row  = (lane & 7) + ((lane & 16) >> 1);
    const int b_cbit = (lane >> 3) & 1;

    const int qb = (gridDim.x - 1) - blockIdx.x;   // heaviest blocks first
    const int bh = blockIdx.y;

    const float* Qg = g_q + ((size_t)bh * Nseq + qb * 64) * Dh;
    const float* Kg = g_k + (size_t)bh * Nseq * Dh;
    const float* Vg = g_v + (size_t)bh * Nseq * Dh;

    const float scale = 0.125f;   // exact on tf32 values (exponent-only)

    const int ntiles = 2 * qb + 2;

    // K tile copy: 32 seq-rows x 64 d -> two swizzled 128B-wide subtiles
    auto cp_k = [&](int j) {
        const float* Kt = Kg + (size_t)j * 32 * Dh;
        float* kb = Ks + (j & 1) * 2048;
#pragma unroll
        for (int i = 0; i < 4; i++) {
            const int idx = tid + i * 128;   // 0..511 (16B chunks)
            const int r   = idx >> 4;        // seq row 0..31
            const int ch  = idx & 15;        // d-chunk 0..15
            const int sub = ch >> 3;
            const int c8  = ch & 7;
            cp16(kb + sub * 1024 + r * 32 + ((c8 ^ (r & 7)) << 2),
                 Kt + r * Dh + ch * 4);
        }
        asm volatile("cp.async.commit_group;");
    };

    float4 vS[4];   // V staging only
    auto ldg_v = [&](int j) {
        const float* Vt = Vg + (size_t)j * 32 * Dh;
#pragma unroll
        for (int i = 0; i < 4; i++) {
            const int idx = tid + i * 128;
            const int r = idx >> 4, c4 = (idx & 15) * 4;
            vS[i] = *(const float4*)(Vt + r * Dh + c4);
        }
    };

    // start first K copy + V load before Q staging (overlap)
    cp_k(0);
    ldg_v(0);

    // Load & pre-scale Q tile (64x64) into A-chunk layout
#pragma unroll
    for (int i = 0; i < 8; i++) {
        const int idx = tid + i * 128;
        const int r = idx >> 4, c4 = (idx & 15) * 4;
        float4 q = *(const float4*)(Qg + r * Dh + c4);
        const int m = r >> 4, gidl = r & 7, half = (r >> 3) & 1;
        const int kg = c4 >> 3, kh = (c4 >> 2) & 1;
        float* qp = Qs + (m * 8 + kg) * 132 + half + 2 * kh;
        const float v[4] = {q.x * scale, q.y * scale, q.z * scale, q.w * scale};
#pragma unroll
        for (int u = 0; u < 4; u++) qp[(gidl * 4 + u) * 4] = v[u];
    }

    float m_top = -INFINITY, m_bot = -INFINITY;
    float l_top = 0.f, l_bot = 0.f;

    float oacc[8][4];
#pragma unroll
    for (int nj = 0; nj < 8; nj++)
#pragma unroll
        for (int q = 0; q < 4; q++) oacc[nj][q] = 0.f;

    for (int j = 0; j < ntiles; j++) {
        const float* kb = Ks + (j & 1) * 2048;
        float* vb = Vs + (j & 1) * 2112;

        // V scatter-store into B-chunk layout (vb (j&1) was read in PV(j-1)? no:
        // PV(j-1) read (j-1)&1 — different buffer; safe before the barrier)
#pragma unroll
        for (int i = 0; i < 4; i++) {
            const int idx = tid + i * 128;
            const int r = idx >> 4, c4 = (idx & 15) * 4;
            const int nb = c4 >> 3;
            const int kg = r >> 3, kh = (r >> 2) & 1, tv = r & 3;
            float* vp = vb + (nb * 4 + kg) * 66 + kh;
            const float v[4] = {vS[i].x, vS[i].y, vS[i].z, vS[i].w};
#pragma unroll
            for (int u = 0; u < 4; u++)
                vp[(((c4 & 7) + u) * 4 + tv) * 2] = v[u];
        }
        // own K(j) chunks complete, then barrier publishes K(j)+V(j) to all
        asm volatile("cp.async.wait_group 0;");
        __syncthreads();
        // K(j+1) copy: buffer (j+1)&1 free (all warps finished S(j-1) at barrier)
        if (j + 1 < ntiles) { cp_k(j + 1); ldg_v(j + 1); }

        // ---- S = Qs * Ks^T : A from Qs chunks, B via ldmatrix from K subtiles ----
        float sacc[4][4];
#pragma unroll
        for (int nb = 0; nb < 4; nb++)
#pragma unroll
            for (int q = 0; q < 4; q++) sacc[nb][q] = 0.f;

#pragma unroll
        for (int kg = 0; kg < 8; kg++) {
            const float4 av = *(const float4*)(Qs + (w * 8 + kg) * 132 + lane * 4);
            unsigned af[4];
            af[0] = __float_as_uint(av.x); af[1] = __float_as_uint(av.y);
            af[2] = __float_as_uint(av.z); af[3] = __float_as_uint(av.w);

            const float* sub = kb + (kg >> 2) * 1024;
            const int ch = (kg & 3) * 2 + b_cbit;
            unsigned bf[4][2];
#pragma unroll
            for (int nb16 = 0; nb16 < 2; nb16++) {
                const int row = nb16 * 16 + b_row;
                const unsigned sb = (unsigned)__cvta_generic_to_shared(
                    sub + row * 32 + ((ch ^ (row & 7)) << 2));
                ldsm_x4(bf[nb16 * 2][0], bf[nb16 * 2][1],
                        bf[nb16 * 2 + 1][0], bf[nb16 * 2 + 1][1], sb);
            }
#pragma unroll
            for (int nb = 0; nb < 4; nb++)
                mma_tf32(sacc[nb], af, bf[nb]);
        }

        // causal mask
        if (j >= 2 * qb) {
            const int r0g = qb * 64 + w * 16 + gid;
            const int r1g = r0g + 8;
#pragma unroll
            for (int nb = 0; nb < 4; nb++) {
                const int cg = j * 32 + nb * 8 + 2 * tig;
                if (cg     > r0g) sacc[nb][0] = -INFINITY;
                if (cg + 1 > r0g) sacc[nb][1] = -INFINITY;
                if (cg     > r1g) sacc[nb][2] = -INFINITY;
                if (cg + 1 > r1g) sacc[nb][3] = -INFINITY;
            }
        }

        // ---- online softmax (quad shuffles) ----
        float mt_t = m_top, mt_b = m_bot;
#pragma unroll
        for (int nb = 0; nb < 4; nb++) {
            mt_t = fmaxf(mt_t, fmaxf(sacc[nb][0], sacc[nb][1]));
            mt_b = fmaxf(mt_b, fmaxf(sacc[nb][2], sacc[nb][3]));
        }
        mt_t = fmaxf(mt_t, __shfl_xor_sync(0xffffffffu, mt_t, 1));
        mt_t = fmaxf(mt_t, __shfl_xor_sync(0xffffffffu, mt_t, 2));
        mt_b = fmaxf(mt_b, __shfl_xor_sync(0xffffffffu, mt_b, 1));
        mt_b = fmaxf(mt_b, __shfl_xor_sync(0xffffffffu, mt_b, 2));

        const bool nochange = (mt_t == m_top) && (mt_b == m_bot);
        const float sc_t = nochange ? 1.f : __expf(m_top - mt_t);
        const float sc_b = nochange ? 1.f : __expf(m_bot - mt_b);
        float ps_t = 0.f, ps_b = 0.f;

        float* sbase = Ss + w * 4 * 132;
#pragma unroll
        for (int nb = 0; nb < 4; nb++) {
            float p[4];
            p[0] = __expf(sacc[nb][0] - mt_t);
            p[1] = __expf(sacc[nb][1] - mt_t);
            p[2] = __expf(sacc[nb][2] - mt_b);
            p[3] = __expf(sacc[nb][3] - mt_b);
            ps_t += p[0] + p[1];
            ps_b += p[2] + p[3];
#pragma unroll
            for (int q = 0; q < 4; q++) {
                const int par  = q & 1;
                const int half = q >> 1;
                const int kin  = 2 * tig + par;
                const int tigA = kin & 3;
                const int khA  = kin >> 2;
                sbase[nb * 132 + (gid * 4 + tigA) * 4 + half + 2 * khA] = f2tf32(p[q]);
            }
        }
        ps_t += __shfl_xor_sync(0xffffffffu, ps_t, 1);
        ps_t += __shfl_xor_sync(0xffffffffu, ps_t, 2);
        ps_b += __shfl_xor_sync(0xffffffffu, ps_b, 1);
        ps_b += __shfl_xor_sync(0xffffffffu, ps_b, 2);

        l_top = l_top * sc_t + ps_t;  m_top = mt_t;
        l_bot = l_bot * sc_b + ps_b;  m_bot = mt_b;

        __syncwarp();

        // ---- O = O*rescale + P*V (skip rescale when max unchanged warp-wide) ----
        if (!__all_sync(0xffffffffu, nochange)) {
#pragma unroll
            for (int nj = 0; nj < 8; nj++) {
                oacc[nj][0] *= sc_t; oacc[nj][1] *= sc_t;
                oacc[nj][2] *= sc_b; oacc[nj][3] *= sc_b;
            }
        }
#pragma unroll
        for (int kg = 0; kg < 4; kg++) {
            const float4 av = *(const float4*)(sbase + kg * 132 + lane * 4);
            unsigned af[4];
            af[0] = __float_as_uint(av.x); af[1] = __float_as_uint(av.y);
            af[2] = __float_as_uint(av.z); af[3] = __float_as_uint(av.w);
#pragma unroll
            for (int nb = 0; nb < 8; nb++) {
                const float2 bv = *(const float2*)(vb + (nb * 4 + kg) * 66 + lane * 2);
                unsigned bf[2];
                bf[0] = __float_as_uint(bv.x); bf[1] = __float_as_uint(bv.y);
                mma_tf32(oacc[nb], af, bf);
            }
        }
        // no end-of-loop sync: next iteration writes the other K/V buffer
    }

    const int b = bh >> 4, h = bh & 15;
    const float inv_top = 1.f / l_top;
    const float inv_bot = 1.f / l_bot;
    const int n_top = qb * 64 + w * 16 + gid;
    const int n_bot = n_top + 8;
#pragma unroll
    for (int nj = 0; nj < 8; nj++) {
        const int c = nj * 8 + 2 * tig;
        float2 v0, v1;
        v0.x = f2tf32(oacc[nj][0] * inv_top); v0.y = f2tf32(oacc[nj][1] * inv_top);
        v1.x = f2tf32(oacc[nj][2] * inv_bot); v1.y = f2tf32(oacc[nj][3] * inv_bot);
        *(float2*)(g_ao + ((size_t)(b * Nseq + n_top)) * (Hh * Dh) + h * Dh + c) = v0;
        *(float2*)(g_ao + ((size_t)(b * Nseq + n_bot)) * (Hh * Dh) + h * Dh + c) = v1;
    }
}

// ---------------------------------------------------------------------------
extern "C" void kernel_launch(void* const* d_in, const int* in_sizes, int n_in,
                              void* d_out, int out_size)
{
    const float* x    = (const float*)d_in[0];
    const float* Wqkv = (const float*)d_in[1];
    const float* bqkv = (const float*)d_in[2];
    const float* Wout = (const float*)d_in[3];
    const float* bout = (const float*)d_in[4];
    float* out = (float*)d_out;

    // raise dynamic smem limits (idempotent)
    cudaFuncSetAttribute(gemm_tf32_kernel<0>, cudaFuncAttributeMaxDynamicSharedMemorySize, 65536);
    cudaFuncSetAttribute(gemm_tf32_kernel<1>, cudaFuncAttributeMaxDynamicSharedMemorySize, 65536);
    cudaFuncSetAttribute(flash_kernel, cudaFuncAttributeMaxDynamicSharedMemorySize, 58624);

    float *gx, *gwq, *gwo;
    cudaGetSymbolAddress((void**)&gx,  g_x);
    cudaGetSymbolAddress((void**)&gwq, g_wq);
    cudaGetSymbolAddress((void**)&gwo, g_wo);

    // K0: tf32 pre-conversion (single launch)
    const int n1 = Bsz * Nseq * Emb / 4;
    const int n2 = 3 * Hh * Dh * Emb / 4;
    const int n3 = Emb * Hh * Dh / 4;
    cvt_tf32_kernel<<<(n1 + n2 + n3 + 255) / 256, 256>>>(
        (const float4*)x, (float4*)gx, n1,
        (const float4*)Wqkv, (float4*)gwq, n2,
        (const float4*)Wout, (float4*)gwo, n3);

    // K1: QKV projection + de-interleave scatter. C is [4096, 3072].
    gemm_tf32_kernel<0><<<dim3(3072 / 128, 4096 / 128), 256, 65536>>>(bqkv, nullptr);

    // K2: causal flash attention. grid (N/64, B*H).
    flash_kernel<<<dim3(Nseq / 64, Bsz * Hh), 128, 58624>>>();

    // K3: output projection. C is [4096, 1024].
    gemm_tf32_kernel<1><<<dim3(1024 / 128, 4096 / 128), 256, 65536>>>(bout, out);
}

// round 15
// speedup vs baseline: 1.2526x; 1.1128x over previous
#include <cuda_runtime.h>
#include <math.h>

#define Bsz  2
#define Nseq 2048
#define Emb  1024
#define Hh   16
#define Dh   64

// Scratch (allocation-free: __device__ globals)
__device__ float g_q [Bsz * Hh * Nseq * Dh];   // [B,H,N,D] (tf32-rounded)
__device__ float g_k [Bsz * Hh * Nseq * Dh];   // [B,H,N,D]
__device__ float g_v [Bsz * Hh * Nseq * Dh];   // [B,H,D,N]  (TRANSPOSED, tf32-rounded)
__device__ float g_ao[Bsz * Nseq * Hh * Dh];   // [B,N,H*D] (tf32-rounded)
__device__ float g_x [Bsz * Nseq * Emb];       // tf32-rounded x
__device__ float g_wq[3 * Hh * Dh * Emb];      // tf32-rounded Wqkv
__device__ float g_wo[Emb * Hh * Dh];          // tf32-rounded Wout

// ---------------------------------------------------------------------------
// helpers
// ---------------------------------------------------------------------------
__device__ __forceinline__ float f2tf32(float f) {
    unsigned r;
    asm("cvt.rna.tf32.f32 %0, %1;" : "=r"(r) : "f"(f));
    return __uint_as_float(r);
}

__device__ __forceinline__ void mma_tf32(float* c, const unsigned* a, const unsigned* b) {
    asm volatile(
        "mma.sync.aligned.m16n8k8.row.col.f32.tf32.tf32.f32 "
        "{%0,%1,%2,%3},{%4,%5,%6,%7},{%8,%9},{%0,%1,%2,%3};"
        : "+f"(c[0]), "+f"(c[1]), "+f"(c[2]), "+f"(c[3])
        : "r"(a[0]), "r"(a[1]), "r"(a[2]), "r"(a[3]), "r"(b[0]), "r"(b[1]));
}

__device__ __forceinline__ void ldsm_x4(unsigned& r0, unsigned& r1, unsigned& r2, unsigned& r3,
                                        unsigned saddr) {
    asm volatile("ldmatrix.sync.aligned.m8n8.x4.shared.b16 {%0,%1,%2,%3}, [%4];"
                 : "=r"(r0), "=r"(r1), "=r"(r2), "=r"(r3) : "r"(saddr));
}

__device__ __forceinline__ void cp16(void* dst_smem, const void* src_gmem) {
    unsigned d = (unsigned)__cvta_generic_to_shared(dst_smem);
    asm volatile("cp.async.cg.shared.global [%0], [%1], 16;" :: "r"(d), "l"(src_gmem));
}

// ---------------------------------------------------------------------------
// tf32 pre-convert pass (all three tensors in one launch)
// ---------------------------------------------------------------------------
__global__ void cvt_tf32_kernel(const float4* __restrict__ x_in,  float4* __restrict__ x_out,  int n1,
                                const float4* __restrict__ wq_in, float4* __restrict__ wq_out, int n2,
                                const float4* __restrict__ wo_in, float4* __restrict__ wo_out, int n3)
{
    const int i = blockIdx.x * 256 + threadIdx.x;
    const float4* src; float4* dst; int idx;
    if (i < n1)            { src = x_in;  dst = x_out;  idx = i; }
    else if (i < n1 + n2)  { src = wq_in; dst = wq_out; idx = i - n1; }
    else if (i < n1 + n2 + n3) { src = wo_in; dst = wo_out; idx = i - n1 - n2; }
    else return;
    float4 v = src[idx];
    float4 r;
    r.x = f2tf32(v.x); r.y = f2tf32(v.y); r.z = f2tf32(v.z); r.w = f2tf32(v.w);
    dst[idx] = r;
}

// ---------------------------------------------------------------------------
// TF32 GEMM (R5 config — best measured). MODE 0 now writes g_v TRANSPOSED
// ([B,H,D,N]) — same scattered 4B stores, different addresses, zero cost.
// 128x128 block tile, BK=32, 256 threads = 8 warps (4 x 2), warp tile 32x64.
// cp.async 2-stage pipeline, 128B-swizzled smem, ldmatrix fragment loads.
// Dynamic smem: 2*(128*32)*2 floats = 64 KB.
// ---------------------------------------------------------------------------
template <int MODE>
__global__ void __launch_bounds__(256, 2) gemm_tf32_kernel(const float* __restrict__ bias,
                                                           float* __restrict__ out)
{
    extern __shared__ float smem[];
    float* Asm = smem;          // 2 stages x 4096 floats
    float* Wsm = smem + 8192;   // 2 stages x 4096 floats

    const float* Ain = (MODE == 0) ? g_x  : g_ao;
    const float* Win = (MODE == 0) ? g_wq : g_wo;

    const int tid  = threadIdx.x;
    const int lane = tid & 31;
    const int warp = tid >> 5;
    const int wm   = warp & 3;         // 0..3 : 32-row group
    const int wn   = warp >> 2;        // 0..1 : 64-col group
    const int bm = blockIdx.y * 128;
    const int bn = blockIdx.x * 128;

    const int gid = lane >> 2;
    const int tig = lane & 3;

    // ldmatrix per-lane address components
    const int a_row  = lane & 15;
    const int a_cbit = lane >> 4;
    const int b_row  = (lane & 7) + ((lane & 16) >> 1);
    const int b_cbit = (lane >> 3) & 1;

    float acc[2][8][4];
#pragma unroll
    for (int mi = 0; mi < 2; mi++)
#pragma unroll
        for (int nj = 0; nj < 8; nj++)
#pragma unroll
            for (int q = 0; q < 4; q++) acc[mi][nj][q] = 0.f;

    auto cp_tile = [&](int kt, int stage) {
        const float* Ab = Ain + (size_t)bm * Emb + kt * 32;
        const float* Wb = Win + (size_t)bn * Emb + kt * 32;
        float* as = Asm + stage * 4096;
        float* ws = Wsm + stage * 4096;
#pragma unroll
        for (int i = 0; i < 4; i++) {
            const int idx = tid + i * 256;          // 0..1023
            const int row = idx >> 3;               // 0..127
            const int ch  = idx & 7;                // 16B chunk
            const int off = row * 32 + ((ch ^ (row & 7)) << 2);
            cp16(as + off, Ab + (size_t)row * Emb + ch * 4);
            cp16(ws + off, Wb + (size_t)row * Emb + ch * 4);
        }
        asm volatile("cp.async.commit_group;");
    };

    const int NT = Emb / 32;
    cp_tile(0, 0);

    for (int kt = 0; kt < NT; kt++) {
        if (kt + 1 < NT) {
            cp_tile(kt + 1, (kt + 1) & 1);
            asm volatile("cp.async.wait_group 1;");
        } else {
            asm volatile("cp.async.wait_group 0;");
        }
        __syncthreads();

        const float* as = Asm + (kt & 1) * 4096;
        const float* ws = Wsm + (kt & 1) * 4096;

#pragma unroll
        for (int kk8 = 0; kk8 < 4; kk8++) {
            unsigned afrag[2][4];
#pragma unroll
            for (int mi = 0; mi < 2; mi++) {
                const int row = wm * 32 + mi * 16 + a_row;
                const int ch  = kk8 * 2 + a_cbit;
                const unsigned sa = (unsigned)__cvta_generic_to_shared(
                    as + row * 32 + ((ch ^ (row & 7)) << 2));
                ldsm_x4(afrag[mi][0], afrag[mi][1], afrag[mi][2], afrag[mi][3], sa);
            }
            unsigned bfrag[8][2];
#pragma unroll
            for (int nj2 = 0; nj2 < 4; nj2++) {
                const int row = wn * 64 + nj2 * 16 + b_row;
                const int ch  = kk8 * 2 + b_cbit;
                const unsigned sb = (unsigned)__cvta_generic_to_shared(
                    ws + row * 32 + ((ch ^ (row & 7)) << 2));
                ldsm_x4(bfrag[nj2 * 2][0], bfrag[nj2 * 2][1],
                        bfrag[nj2 * 2 + 1][0], bfrag[nj2 * 2 + 1][1], sb);
            }
#pragma unroll
            for (int mi = 0; mi < 2; mi++)
#pragma unroll
                for (int nj = 0; nj < 8; nj++)
                    mma_tf32(acc[mi][nj], afrag[mi], bfrag[nj]);
        }
        __syncthreads();
    }

    // epilogue
#pragma unroll
    for (int mi = 0; mi < 2; mi++) {
        const int r_top = bm + wm * 32 + mi * 16 + gid;
        const int r_bot = r_top + 8;
#pragma unroll
        for (int nj = 0; nj < 8; nj++) {
            const int c = bn + wn * 64 + nj * 8 + 2 * tig;
            if (MODE == 0) {
#pragma unroll
                for (int q = 0; q < 4; q++) {
                    const int row = (q < 2) ? r_top : r_bot;
                    const int col = c + (q & 1);
                    const int b = row >> 11;
                    const int n = row & 2047;
                    const int s = col % 3;
                    const int h = col / 192;
                    const int d = (col % 192) / 3;
                    const float val = f2tf32(acc[mi][nj][q] + bias[col]);
                    if (s == 2) {
                        // V transposed: [B,H,D,N]
                        g_v[(((size_t)(b * Hh + h)) * Dh + d) * Nseq + n] = val;
                    } else {
                        float* dst = (s == 0) ? g_q : g_k;
                        dst[(((size_t)(b * Hh + h)) * Nseq + n) * Dh + d] = val;
                    }
                }
            } else {
                const float2 bv = *(const float2*)(bias + c);
                float2 v0, v1;
                v0.x = acc[mi][nj][0] + bv.x; v0.y = acc[mi][nj][1] + bv.y;
                v1.x = acc[mi][nj][2] + bv.x; v1.y = acc[mi][nj][3] + bv.y;
                *(float2*)(out + (size_t)r_top * Emb + c) = v0;
                *(float2*)(out + (size_t)r_bot * Emb + c) = v1;
            }
        }
    }
}

// ---------------------------------------------------------------------------
// Flash attention v3: BOTH K and V via cp.async + swizzled tiles + ldmatrix.
// V is pre-transposed ([B,H,D,N]) by K1, so its tile is rows=d (64 x 128B) —
// exactly the GEMM W-tile shape; PV B-fragments come from ldmatrix.
// grid = (N/64, B*H), 128 threads = 4 warps. BR=64, BC=32.
// Dynamic smem: 4224 (Qs) + 2*2048 (Ks) + 2*2048 (Vs) + 2112 (Ss)
//             = 14528 floats = 58112 B. 2 CTAs/SM.
// ---------------------------------------------------------------------------
__global__ void __launch_bounds__(128, 2) flash_kernel()
{
    extern __shared__ float fsm[];
    float* Qs = fsm;            // A-chunks (m 0..3, kg 0..7): 4224
    float* Ks = fsm + 4224;     // 2 bufs x swizzled K subtiles: 2048 each
    float* Vs = fsm + 8320;     // 2 bufs x swizzled V^T tiles (64 rows x 128B): 2048 each
    float* Ss = fsm + 12416;    // A-chunks per warp: 2112

    const int tid  = threadIdx.x;
    const int lane = tid & 31;
    const int w    = tid >> 5;
    const int gid  = lane >> 2;
    const int tig  = lane & 3;

    // ldmatrix B per-lane address components (same as GEMM)
    const int b_row  = (lane & 7) + ((lane & 16) >> 1);
    const int b_cbit = (lane >> 3) & 1;

    const int qb = (gridDim.x - 1) - blockIdx.x;   // heaviest blocks first
    const int bh = blockIdx.y;

    const float* Qg = g_q + ((size_t)bh * Nseq + qb * 64) * Dh;
    const float* Kg = g_k + (size_t)bh * Nseq * Dh;
    const float* Vg = g_v + (size_t)bh * Dh * Nseq;   // transposed: rows=d

    const float scale = 0.125f;   // exact on tf32 values (exponent-only)

    const int ntiles = 2 * qb + 2;

    // K tile copy: 32 seq-rows x 64 d -> two swizzled 128B-wide subtiles
    auto cp_k = [&](int j) {
        const float* Kt = Kg + (size_t)j * 32 * Dh;
        float* kb = Ks + (j & 1) * 2048;
#pragma unroll
        for (int i = 0; i < 4; i++) {
            const int idx = tid + i * 128;   // 0..511 (16B chunks)
            const int r   = idx >> 4;        // seq row 0..31
            const int ch  = idx & 15;        // d-chunk 0..15
            const int sub = ch >> 3;
            const int c8  = ch & 7;
            cp16(kb + sub * 1024 + r * 32 + ((c8 ^ (r & 7)) << 2),
                 Kt + r * Dh + ch * 4);
        }
        asm volatile("cp.async.commit_group;");
    };

    // V^T tile copy: 64 d-rows x 32 seq -> one swizzled tile (row stride Nseq)
    auto cp_v = [&](int j) {
        const float* Vt = Vg + (size_t)j * 32;
        float* vb = Vs + (j & 1) * 2048;
#pragma unroll
        for (int i = 0; i < 4; i++) {
            const int idx = tid + i * 128;   // 0..511 (16B chunks)
            const int r   = idx >> 3;        // d row 0..63
            const int ch  = idx & 7;         // seq chunk 0..7
            cp16(vb + r * 32 + ((ch ^ (r & 7)) << 2),
                 Vt + (size_t)r * Nseq + ch * 4);
        }
        asm volatile("cp.async.commit_group;");
    };

    // start first K+V copies before Q staging (overlap)
    cp_k(0);
    cp_v(0);

    // Load & pre-scale Q tile (64x64) into A-chunk layout
#pragma unroll
    for (int i = 0; i < 8; i++) {
        const int idx = tid + i * 128;
        const int r = idx >> 4, c4 = (idx & 15) * 4;
        float4 q = *(const float4*)(Qg + r * Dh + c4);
        const int m = r >> 4, gidl = r & 7, half = (r >> 3) & 1;
        const int kg = c4 >> 3, kh = (c4 >> 2) & 1;
        float* qp = Qs + (m * 8 + kg) * 132 + half + 2 * kh;
        const float v[4] = {q.x * scale, q.y * scale, q.z * scale, q.w * scale};
#pragma unroll
        for (int u = 0; u < 4; u++) qp[(gidl * 4 + u) * 4] = v[u];
    }

    float m_top = -INFINITY, m_bot = -INFINITY;
    float l_top = 0.f, l_bot = 0.f;

    float oacc[8][4];
#pragma unroll
    for (int nj = 0; nj < 8; nj++)
#pragma unroll
        for (int q = 0; q < 4; q++) oacc[nj][q] = 0.f;

    for (int j = 0; j < ntiles; j++) {
        const float* kb = Ks + (j & 1) * 2048;
        const float* vb = Vs + (j & 1) * 2048;

        // K(j)+V(j) chunks complete, then barrier publishes to all warps
        asm volatile("cp.async.wait_group 0;");
        __syncthreads();
        // buffers (j+1)&1 free: all warps finished S(j-1)/PV(j-1) at this barrier
        if (j + 1 < ntiles) { cp_k(j + 1); cp_v(j + 1); }

        // ---- S = Qs * Ks^T : A from Qs chunks, B via ldmatrix from K subtiles ----
        float sacc[4][4];
#pragma unroll
        for (int nb = 0; nb < 4; nb++)
#pragma unroll
            for (int q = 0; q < 4; q++) sacc[nb][q] = 0.f;

#pragma unroll
        for (int kg = 0; kg < 8; kg++) {
            const float4 av = *(const float4*)(Qs + (w * 8 + kg) * 132 + lane * 4);
            unsigned af[4];
            af[0] = __float_as_uint(av.x); af[1] = __float_as_uint(av.y);
            af[2] = __float_as_uint(av.z); af[3] = __float_as_uint(av.w);

            const float* sub = kb + (kg >> 2) * 1024;
            const int ch = (kg & 3) * 2 + b_cbit;
            unsigned bf[4][2];
#pragma unroll
            for (int nb16 = 0; nb16 < 2; nb16++) {
                const int row = nb16 * 16 + b_row;
                const unsigned sb = (unsigned)__cvta_generic_to_shared(
                    sub + row * 32 + ((ch ^ (row & 7)) << 2));
                ldsm_x4(bf[nb16 * 2][0], bf[nb16 * 2][1],
                        bf[nb16 * 2 + 1][0], bf[nb16 * 2 + 1][1], sb);
            }
#pragma unroll
            for (int nb = 0; nb < 4; nb++)
                mma_tf32(sacc[nb], af, bf[nb]);
        }

        // causal mask
        if (j >= 2 * qb) {
            const int r0g = qb * 64 + w * 16 + gid;
            const int r1g = r0g + 8;
#pragma unroll
            for (int nb = 0; nb < 4; nb++) {
                const int cg = j * 32 + nb * 8 + 2 * tig;
                if (cg     > r0g) sacc[nb][0] = -INFINITY;
                if (cg + 1 > r0g) sacc[nb][1] = -INFINITY;
                if (cg     > r1g) sacc[nb][2] = -INFINITY;
                if (cg + 1 > r1g) sacc[nb][3] = -INFINITY;
            }
        }

        // ---- online softmax (quad shuffles) ----
        float mt_t = m_top, mt_b = m_bot;
#pragma unroll
        for (int nb = 0; nb < 4; nb++) {
            mt_t = fmaxf(mt_t, fmaxf(sacc[nb][0], sacc[nb][1]));
            mt_b = fmaxf(mt_b, fmaxf(sacc[nb][2], sacc[nb][3]));
        }
        mt_t = fmaxf(mt_t, __shfl_xor_sync(0xffffffffu, mt_t, 1));
        mt_t = fmaxf(mt_t, __shfl_xor_sync(0xffffffffu, mt_t, 2));
        mt_b = fmaxf(mt_b, __shfl_xor_sync(0xffffffffu, mt_b, 1));
        mt_b = fmaxf(mt_b, __shfl_xor_sync(0xffffffffu, mt_b, 2));

        const bool nochange = (mt_t == m_top) && (mt_b == m_bot);
        const float sc_t = nochange ? 1.f : __expf(m_top - mt_t);
        const float sc_b = nochange ? 1.f : __expf(m_bot - mt_b);
        float ps_t = 0.f, ps_b = 0.f;

        float* sbase = Ss + w * 4 * 132;
#pragma unroll
        for (int nb = 0; nb < 4; nb++) {
            float p[4];
            p[0] = __expf(sacc[nb][0] - mt_t);
            p[1] = __expf(sacc[nb][1] - mt_t);
            p[2] = __expf(sacc[nb][2] - mt_b);
            p[3] = __expf(sacc[nb][3] - mt_b);
            ps_t += p[0] + p[1];
            ps_b += p[2] + p[3];
#pragma unroll
            for (int q = 0; q < 4; q++) {
                const int par  = q & 1;
                const int half = q >> 1;
                const int kin  = 2 * tig + par;
                const int tigA = kin & 3;
                const int khA  = kin >> 2;
                sbase[nb * 132 + (gid * 4 + tigA) * 4 + half + 2 * khA] = f2tf32(p[q]);
            }
        }
        ps_t += __shfl_xor_sync(0xffffffffu, ps_t, 1);
        ps_t += __shfl_xor_sync(0xffffffffu, ps_t, 2);
        ps_b += __shfl_xor_sync(0xffffffffu, ps_b, 1);
        ps_b += __shfl_xor_sync(0xffffffffu, ps_b, 2);

        l_top = l_top * sc_t + ps_t;  m_top = mt_t;
        l_bot = l_bot * sc_b + ps_b;  m_bot = mt_b;

        __syncwarp();

        // ---- O = O*rescale + P*V (skip rescale when max unchanged warp-wide) ----
        if (!__all_sync(0xffffffffu, nochange)) {
#pragma unroll
            for (int nj = 0; nj < 8; nj++) {
                oacc[nj][0] *= sc_t; oacc[nj][1] *= sc_t;
                oacc[nj][2] *= sc_b; oacc[nj][3] *= sc_b;
            }
        }
        // B fragments via ldmatrix from V^T tile (n=d rows, k=seq chunks)
#pragma unroll
        for (int kg = 0; kg < 4; kg++) {
            const float4 av = *(const float4*)(sbase + kg * 132 + lane * 4);
            unsigned af[4];
            af[0] = __float_as_uint(av.x); af[1] = __float_as_uint(av.y);
            af[2] = __float_as_uint(av.z); af[3] = __float_as_uint(av.w);

            const int ch = kg * 2 + b_cbit;
            unsigned bf[8][2];
#pragma unroll
            for (int nb16 = 0; nb16 < 4; nb16++) {
                const int row = nb16 * 16 + b_row;
                const unsigned sb = (unsigned)__cvta_generic_to_shared(
                    vb + row * 32 + ((ch ^ (row & 7)) << 2));
                ldsm_x4(bf[nb16 * 2][0], bf[nb16 * 2][1],
                        bf[nb16 * 2 + 1][0], bf[nb16 * 2 + 1][1], sb);
            }
#pragma unroll
            for (int nb = 0; nb < 8; nb++)
                mma_tf32(oacc[nb], af, bf[nb]);
        }
        // no end-of-loop sync: next iteration's barrier orders buffer reuse
    }

    const int b = bh >> 4, h = bh & 15;
    const float inv_top = 1.f / l_top;
    const float inv_bot = 1.f / l_bot;
    const int n_top = qb * 64 + w * 16 + gid;
    const int n_bot = n_top + 8;
#pragma unroll
    for (int nj = 0; nj < 8; nj++) {
        const int c = nj * 8 + 2 * tig;
        float2 v0, v1;
        v0.x = f2tf32(oacc[nj][0] * inv_top); v0.y = f2tf32(oacc[nj][1] * inv_top);
        v1.x = f2tf32(oacc[nj][2] * inv_bot); v1.y = f2tf32(oacc[nj][3] * inv_bot);
        *(float2*)(g_ao + ((size_t)(b * Nseq + n_top)) * (Hh * Dh) + h * Dh + c) = v0;
        *(float2*)(g_ao + ((size_t)(b * Nseq + n_bot)) * (Hh * Dh) + h * Dh + c) = v1;
    }
}

// ---------------------------------------------------------------------------
extern "C" void kernel_launch(void* const* d_in, const int* in_sizes, int n_in,
                              void* d_out, int out_size)
{
    const float* x    = (const float*)d_in[0];
    const float* Wqkv = (const float*)d_in[1];
    const float* bqkv = (const float*)d_in[2];
    const float* Wout = (const float*)d_in[3];
    const float* bout = (const float*)d_in[4];
    float* out = (float*)d_out;

    // raise dynamic smem limits (idempotent)
    cudaFuncSetAttribute(gemm_tf32_kernel<0>, cudaFuncAttributeMaxDynamicSharedMemorySize, 65536);
    cudaFuncSetAttribute(gemm_tf32_kernel<1>, cudaFuncAttributeMaxDynamicSharedMemorySize, 65536);
    cudaFuncSetAttribute(flash_kernel, cudaFuncAttributeMaxDynamicSharedMemorySize, 58112);

    float *gx, *gwq, *gwo;
    cudaGetSymbolAddress((void**)&gx,  g_x);
    cudaGetSymbolAddress((void**)&gwq, g_wq);
    cudaGetSymbolAddress((void**)&gwo, g_wo);

    // K0: tf32 pre-conversion (single launch)
    const int n1 = Bsz * Nseq * Emb / 4;
    const int n2 = 3 * Hh * Dh * Emb / 4;
    const int n3 = Emb * Hh * Dh / 4;
    cvt_tf32_kernel<<<(n1 + n2 + n3 + 255) / 256, 256>>>(
        (const float4*)x, (float4*)gx, n1,
        (const float4*)Wqkv, (float4*)gwq, n2,
        (const float4*)Wout, (float4*)gwo, n3);

    // K1: QKV projection + de-interleave scatter (V transposed). C is [4096, 3072].
    gemm_tf32_kernel<0><<<dim3(3072 / 128, 4096 / 128), 256, 65536>>>(bqkv, nullptr);

    // K2: causal flash attention. grid (N/64, B*H).
    flash_kernel<<<dim3(Nseq / 64, Bsz * Hh), 128, 58112>>>();

    // K3: output projection. C is [4096, 1024].
    gemm_tf32_kernel<1><<<dim3(1024 / 128, 4096 / 128), 256, 65536>>>(bout, out);
}

// round 16
// speedup vs baseline: 2.0156x; 1.6092x over previous
#include <cuda_runtime.h>
#include <cuda_fp16.h>
#include <math.h>

#define Bsz  2
#define Nseq 2048
#define Emb  1024
#define Hh   16
#define Dh   64

// Scratch (allocation-free: __device__ globals) — all fp16 now
__device__ __half g_q [Bsz * Hh * Nseq * Dh];   // [B,H,N,D], pre-scaled by 0.125
__device__ __half g_k [Bsz * Hh * Nseq * Dh];   // [B,H,N,D]
__device__ __half g_v [Bsz * Hh * Nseq * Dh];   // [B,H,D,N]  (TRANSPOSED)
__device__ __half g_ao[Bsz * Nseq * Hh * Dh];   // [B,N,H*D]
__device__ __half g_x [Bsz * Nseq * Emb];
__device__ __half g_wq[3 * Hh * Dh * Emb];
__device__ __half g_wo[Emb * Hh * Dh];

// ---------------------------------------------------------------------------
// helpers
// ---------------------------------------------------------------------------
__device__ __forceinline__ void mma_f16(float* c, const unsigned* a, const unsigned* b) {
    asm volatile(
        "mma.sync.aligned.m16n8k16.row.col.f32.f16.f16.f32 "
        "{%0,%1,%2,%3},{%4,%5,%6,%7},{%8,%9},{%0,%1,%2,%3};"
        : "+f"(c[0]), "+f"(c[1]), "+f"(c[2]), "+f"(c[3])
        : "r"(a[0]), "r"(a[1]), "r"(a[2]), "r"(a[3]), "r"(b[0]), "r"(b[1]));
}

__device__ __forceinline__ void ldsm_x4(unsigned& r0, unsigned& r1, unsigned& r2, unsigned& r3,
                                        unsigned saddr) {
    asm volatile("ldmatrix.sync.aligned.m8n8.x4.shared.b16 {%0,%1,%2,%3}, [%4];"
                 : "=r"(r0), "=r"(r1), "=r"(r2), "=r"(r3) : "r"(saddr));
}

__device__ __forceinline__ void cp16(void* dst_smem, const void* src_gmem) {
    unsigned d = (unsigned)__cvta_generic_to_shared(dst_smem);
    asm volatile("cp.async.cg.shared.global [%0], [%1], 16;" :: "r"(d), "l"(src_gmem));
}

__device__ __forceinline__ unsigned pk2(float lo, float hi) {
    __half2 h = __floats2half2_rn(lo, hi);
    return *reinterpret_cast<unsigned*>(&h);
}

// ---------------------------------------------------------------------------
// fp16 pre-convert pass (all three tensors in one launch)
// ---------------------------------------------------------------------------
__global__ void cvt_f16_kernel(const float4* __restrict__ x_in,  __half* __restrict__ x_out,  int n1,
                               const float4* __restrict__ wq_in, __half* __restrict__ wq_out, int n2,
                               const float4* __restrict__ wo_in, __half* __restrict__ wo_out, int n3)
{
    const int i = blockIdx.x * 256 + threadIdx.x;
    const float4* src; __half* dst; int idx;
    if (i < n1)            { src = x_in;  dst = x_out;  idx = i; }
    else if (i < n1 + n2)  { src = wq_in; dst = wq_out; idx = i - n1; }
    else if (i < n1 + n2 + n3) { src = wo_in; dst = wo_out; idx = i - n1 - n2; }
    else return;
    float4 v = src[idx];
    __half2* d2 = (__half2*)(dst + (size_t)idx * 4);
    d2[0] = __floats2half2_rn(v.x, v.y);
    d2[1] = __floats2half2_rn(v.z, v.w);
}

// ---------------------------------------------------------------------------
// FP16 GEMM: C[r][c] = sum_k A[r][k] * W[c][k] + bias[c]   (fp32 accum)
// 128x128 block tile, BK=64, 256 threads = 8 warps (4 x 2), warp tile 32x64.
// cp.async 2-stage pipeline, 128B-swizzled smem, ldmatrix fragments,
// m16n8k16 HMMA. MODE 0 scatters fp16 q (x0.125) / k / v-transposed;
// MODE 1 writes fp32 out. Dynamic smem: 2 stages x 2 x 16KB = 64 KB.
// ---------------------------------------------------------------------------
template <int MODE>
__global__ void __launch_bounds__(256, 2) gemm_f16_kernel(const float* __restrict__ bias,
                                                          float* __restrict__ out)
{
    extern __shared__ __half hsm[];
    __half* Asm = hsm;            // 2 stages x 8192 halves
    __half* Wsm = hsm + 16384;    // 2 stages x 8192 halves

    const __half* Ain = (MODE == 0) ? g_x  : g_ao;
    const __half* Win = (MODE == 0) ? g_wq : g_wo;

    const int tid  = threadIdx.x;
    const int lane = tid & 31;
    const int warp = tid >> 5;
    const int wm   = warp & 3;         // 0..3 : 32-row group
    const int wn   = warp >> 2;        // 0..1 : 64-col group
    const int bm = blockIdx.y * 128;
    const int bn = blockIdx.x * 128;

    const int gid = lane >> 2;
    const int tig = lane & 3;

    // ldmatrix per-lane address components (proven in tf32 kernels)
    const int a_row  = lane & 15;
    const int a_cbit = lane >> 4;
    const int b_row  = (lane & 7) + ((lane & 16) >> 1);
    const int b_cbit = (lane >> 3) & 1;

    float acc[2][8][4];
#pragma unroll
    for (int mi = 0; mi < 2; mi++)
#pragma unroll
        for (int nj = 0; nj < 8; nj++)
#pragma unroll
            for (int q = 0; q < 4; q++) acc[mi][nj][q] = 0.f;

    auto cp_tile = [&](int kt, int stage) {
        const __half* Ab = Ain + (size_t)bm * Emb + kt * 64;
        const __half* Wb = Win + (size_t)bn * Emb + kt * 64;
        __half* as = Asm + stage * 8192;
        __half* ws = Wsm + stage * 8192;
#pragma unroll
        for (int i = 0; i < 4; i++) {
            const int idx = tid + i * 256;          // 0..1023
            const int row = idx >> 3;               // 0..127
            const int ch  = idx & 7;                // 16B chunk (8 halves)
            const int off = row * 64 + ((ch ^ (row & 7)) << 3);
            cp16(as + off, Ab + (size_t)row * Emb + ch * 8);
            cp16(ws + off, Wb + (size_t)row * Emb + ch * 8);
        }
        asm volatile("cp.async.commit_group;");
    };

    const int NT = Emb / 64;   // 16
    cp_tile(0, 0);

    for (int kt = 0; kt < NT; kt++) {
        if (kt + 1 < NT) {
            cp_tile(kt + 1, (kt + 1) & 1);
            asm volatile("cp.async.wait_group 1;");
        } else {
            asm volatile("cp.async.wait_group 0;");
        }
        __syncthreads();

        const __half* as = Asm + (kt & 1) * 8192;
        const __half* ws = Wsm + (kt & 1) * 8192;

#pragma unroll
        for (int ks = 0; ks < 4; ks++) {           // 4 x k16 = 64 K
            unsigned afrag[2][4];
#pragma unroll
            for (int mi = 0; mi < 2; mi++) {
                const int row = wm * 32 + mi * 16 + a_row;
                const int ch  = ks * 2 + a_cbit;
                const unsigned sa = (unsigned)__cvta_generic_to_shared(
                    as + row * 64 + ((ch ^ (row & 7)) << 3));
                ldsm_x4(afrag[mi][0], afrag[mi][1], afrag[mi][2], afrag[mi][3], sa);
            }
            unsigned bfrag[8][2];
#pragma unroll
            for (int nj2 = 0; nj2 < 4; nj2++) {
                const int row = wn * 64 + nj2 * 16 + b_row;
                const int ch  = ks * 2 + b_cbit;
                const unsigned sb = (unsigned)__cvta_generic_to_shared(
                    ws + row * 64 + ((ch ^ (row & 7)) << 3));
                ldsm_x4(bfrag[nj2 * 2][0], bfrag[nj2 * 2][1],
                        bfrag[nj2 * 2 + 1][0], bfrag[nj2 * 2 + 1][1], sb);
            }
#pragma unroll
            for (int mi = 0; mi < 2; mi++)
#pragma unroll
                for (int nj = 0; nj < 8; nj++)
                    mma_f16(acc[mi][nj], afrag[mi], bfrag[nj]);
        }
        __syncthreads();
    }

    // epilogue
#pragma unroll
    for (int mi = 0; mi < 2; mi++) {
        const int r_top = bm + wm * 32 + mi * 16 + gid;
        const int r_bot = r_top + 8;
#pragma unroll
        for (int nj = 0; nj < 8; nj++) {
            const int c = bn + wn * 64 + nj * 8 + 2 * tig;
            if (MODE == 0) {
#pragma unroll
                for (int q = 0; q < 4; q++) {
                    const int row = (q < 2) ? r_top : r_bot;
                    const int col = c + (q & 1);
                    const int b = row >> 11;
                    const int n = row & 2047;
                    const int s = col % 3;
                    const int h = col / 192;
                    const int d = (col % 192) / 3;
                    float val = acc[mi][nj][q] + bias[col];
                    if (s == 0) val *= 0.125f;     // pre-scale Q (exact)
                    const __half hv = __float2half_rn(val);
                    if (s == 2) {
                        g_v[(((size_t)(b * Hh + h)) * Dh + d) * Nseq + n] = hv;  // [B,H,D,N]
                    } else {
                        __half* dst = (s == 0) ? g_q : g_k;
                        dst[(((size_t)(b * Hh + h)) * Nseq + n) * Dh + d] = hv;
                    }
                }
            } else {
                const float2 bv = *(const float2*)(bias + c);
                float2 v0, v1;
                v0.x = acc[mi][nj][0] + bv.x; v0.y = acc[mi][nj][1] + bv.y;
                v1.x = acc[mi][nj][2] + bv.x; v1.y = acc[mi][nj][3] + bv.y;
                *(float2*)(out + (size_t)r_top * Emb + c) = v0;
                *(float2*)(out + (size_t)r_bot * Emb + c) = v1;
            }
        }
    }
}

// ---------------------------------------------------------------------------
// Flash attention v4 (fp16): K/V/Q all cp.async swizzled tiles + ldmatrix,
// m16n8k16 HMMA, and P passed S->PV ENTIRELY IN REGISTERS (C-fragment
// half2-packs == A-fragment layout). No Ss smem. fp32 softmax state.
// grid = (N/64, B*H), 128 threads = 4 warps. BR=64, BC=32.
// Static smem: Q 4096 + K 2x2048 + V(padded rows) 2x4096 = 16384 halves = 32KB.
// ---------------------------------------------------------------------------
__global__ void __launch_bounds__(128, 2) flash_kernel()
{
    __shared__ __half Qs[4096];        // 64 rows x 64 halves (128B rows)
    __shared__ __half Ks[2][2048];     // 32 rows x 64 halves
    __shared__ __half Vs[2][4096];     // 64 d-rows x 64 halves (32 seq used, padded)

    const int tid  = threadIdx.x;
    const int lane = tid & 31;
    const int w    = tid >> 5;
    const int gid  = lane >> 2;
    const int tig  = lane & 3;

    const int a_row  = lane & 15;
    const int a_cbit = lane >> 4;
    const int b_row  = (lane & 7) + ((lane & 16) >> 1);
    const int b_cbit = (lane >> 3) & 1;

    const int qb = (gridDim.x - 1) - blockIdx.x;   // heaviest blocks first
    const int bh = blockIdx.y;

    const __half* Qg = g_q + ((size_t)bh * Nseq + qb * 64) * Dh;
    const __half* Kg = g_k + (size_t)bh * Nseq * Dh;
    const __half* Vg = g_v + (size_t)bh * Dh * Nseq;   // transposed: rows=d

    const int ntiles = 2 * qb + 2;

    auto cp_k = [&](int j) {
        const __half* Kt = Kg + (size_t)j * 32 * Dh;
        __half* kb = Ks[j & 1];
#pragma unroll
        for (int i = 0; i < 2; i++) {
            const int idx = tid + i * 128;   // 0..255
            const int r   = idx >> 3;        // seq row 0..31
            const int ch  = idx & 7;
            cp16(kb + r * 64 + ((ch ^ (r & 7)) << 3), Kt + r * Dh + ch * 8);
        }
        asm volatile("cp.async.commit_group;");
    };
    auto cp_v = [&](int j) {
        const __half* Vt = Vg + (size_t)j * 32;
        __half* vb = Vs[j & 1];
#pragma unroll
        for (int i = 0; i < 2; i++) {
            const int idx = tid + i * 128;   // 0..255
            const int r   = idx >> 2;        // d row 0..63
            const int ch  = idx & 3;         // seq chunk 0..3
            cp16(vb + r * 64 + ((ch ^ (r & 7)) << 3), Vt + (size_t)r * Nseq + ch * 8);
        }
        asm volatile("cp.async.commit_group;");
    };

    // Q tile copy (pre-scaled by K1)
    {
#pragma unroll
        for (int i = 0; i < 4; i++) {
            const int idx = tid + i * 128;   // 0..511
            const int r   = idx >> 3;        // 0..63
            const int ch  = idx & 7;
            cp16(Qs + r * 64 + ((ch ^ (r & 7)) << 3), Qg + r * Dh + ch * 8);
        }
        asm volatile("cp.async.commit_group;");
    }
    cp_k(0);
    cp_v(0);

    float m_top = -INFINITY, m_bot = -INFINITY;
    float l_top = 0.f, l_bot = 0.f;

    float oacc[8][4];
#pragma unroll
    for (int nj = 0; nj < 8; nj++)
#pragma unroll
        for (int q = 0; q < 4; q++) oacc[nj][q] = 0.f;

    for (int j = 0; j < ntiles; j++) {
        const __half* kb = Ks[j & 1];
        const __half* vb = Vs[j & 1];

        asm volatile("cp.async.wait_group 0;");
        __syncthreads();
        if (j + 1 < ntiles) { cp_k(j + 1); cp_v(j + 1); }

        // ---- S = Q * K^T : m16 (warp rows) x n32, k=64 in 4 k16 steps ----
        float sacc[4][4];
#pragma unroll
        for (int nb = 0; nb < 4; nb++)
#pragma unroll
            for (int q = 0; q < 4; q++) sacc[nb][q] = 0.f;

#pragma unroll
        for (int ks = 0; ks < 4; ks++) {
            unsigned af[4];
            {
                const int row = w * 16 + a_row;
                const int ch  = ks * 2 + a_cbit;
                const unsigned sa = (unsigned)__cvta_generic_to_shared(
                    Qs + row * 64 + ((ch ^ (row & 7)) << 3));
                ldsm_x4(af[0], af[1], af[2], af[3], sa);
            }
            unsigned bf[4][2];
#pragma unroll
            for (int nb16 = 0; nb16 < 2; nb16++) {
                const int row = nb16 * 16 + b_row;
                const int ch  = ks * 2 + b_cbit;
                const unsigned sb = (unsigned)__cvta_generic_to_shared(
                    kb + row * 64 + ((ch ^ (row & 7)) << 3));
                ldsm_x4(bf[nb16 * 2][0], bf[nb16 * 2][1],
                        bf[nb16 * 2 + 1][0], bf[nb16 * 2 + 1][1], sb);
            }
#pragma unroll
            for (int nb = 0; nb < 4; nb++)
                mma_f16(sacc[nb], af, bf[nb]);
        }

        // causal mask
        if (j >= 2 * qb) {
            const int r0g = qb * 64 + w * 16 + gid;
            const int r1g = r0g + 8;
#pragma unroll
            for (int nb = 0; nb < 4; nb++) {
                const int cg = j * 32 + nb * 8 + 2 * tig;
                if (cg     > r0g) sacc[nb][0] = -INFINITY;
                if (cg + 1 > r0g) sacc[nb][1] = -INFINITY;
                if (cg     > r1g) sacc[nb][2] = -INFINITY;
                if (cg + 1 > r1g) sacc[nb][3] = -INFINITY;
            }
        }

        // ---- online softmax (quad shuffles), P packed into A-fragments ----
        float mt_t = m_top, mt_b = m_bot;
#pragma unroll
        for (int nb = 0; nb < 4; nb++) {
            mt_t = fmaxf(mt_t, fmaxf(sacc[nb][0], sacc[nb][1]));
            mt_b = fmaxf(mt_b, fmaxf(sacc[nb][2], sacc[nb][3]));
        }
        mt_t = fmaxf(mt_t, __shfl_xor_sync(0xffffffffu, mt_t, 1));
        mt_t = fmaxf(mt_t, __shfl_xor_sync(0xffffffffu, mt_t, 2));
        mt_b = fmaxf(mt_b, __shfl_xor_sync(0xffffffffu, mt_b, 1));
        mt_b = fmaxf(mt_b, __shfl_xor_sync(0xffffffffu, mt_b, 2));

        const bool nochange = (mt_t == m_top) && (mt_b == m_bot);
        const float sc_t = nochange ? 1.f : __expf(m_top - mt_t);
        const float sc_b = nochange ? 1.f : __expf(m_bot - mt_b);
        float ps_t = 0.f, ps_b = 0.f;

        unsigned paf[2][4];   // P A-fragments: [kstep][a0..a3]
#pragma unroll
        for (int nb = 0; nb < 4; nb++) {
            float p0 = __expf(sacc[nb][0] - mt_t);
            float p1 = __expf(sacc[nb][1] - mt_t);
            float p2 = __expf(sacc[nb][2] - mt_b);
            float p3 = __expf(sacc[nb][3] - mt_b);
            ps_t += p0 + p1;
            ps_b += p2 + p3;
            paf[nb >> 1][(nb & 1) * 2 + 0] = pk2(p0, p1);   // rows gid
            paf[nb >> 1][(nb & 1) * 2 + 1] = pk2(p2, p3);   // rows gid+8
        }
        ps_t += __shfl_xor_sync(0xffffffffu, ps_t, 1);
        ps_t += __shfl_xor_sync(0xffffffffu, ps_t, 2);
        ps_b += __shfl_xor_sync(0xffffffffu, ps_b, 1);
        ps_b += __shfl_xor_sync(0xffffffffu, ps_b, 2);

        l_top = l_top * sc_t + ps_t;  m_top = mt_t;
        l_bot = l_bot * sc_b + ps_b;  m_bot = mt_b;

        // ---- O = O*rescale + P*V (P from registers; V^T via ldmatrix) ----
        if (!__all_sync(0xffffffffu, nochange)) {
#pragma unroll
            for (int nj = 0; nj < 8; nj++) {
                oacc[nj][0] *= sc_t; oacc[nj][1] *= sc_t;
                oacc[nj][2] *= sc_b; oacc[nj][3] *= sc_b;
            }
        }
#pragma unroll
        for (int ks = 0; ks < 2; ks++) {           // k=seq32 in 2 k16 steps
            unsigned bf[8][2];
#pragma unroll
            for (int nj2 = 0; nj2 < 4; nj2++) {
                const int row = nj2 * 16 + b_row;  // d rows 0..63
                const int ch  = ks * 2 + b_cbit;   // seq chunks 0..3
                const unsigned sb = (unsigned)__cvta_generic_to_shared(
                    vb + row * 64 + ((ch ^ (row & 7)) << 3));
                ldsm_x4(bf[nj2 * 2][0], bf[nj2 * 2][1],
                        bf[nj2 * 2 + 1][0], bf[nj2 * 2 + 1][1], sb);
            }
#pragma unroll
            for (int nb = 0; nb < 8; nb++)
                mma_f16(oacc[nb], paf[ks], bf[nb]);
        }
        // no end-of-loop sync: next iteration's barrier orders buffer reuse
    }

    const int b = bh >> 4, h = bh & 15;
    const float inv_top = 1.f / l_top;
    const float inv_bot = 1.f / l_bot;
    const int n_top = qb * 64 + w * 16 + gid;
    const int n_bot = n_top + 8;
#pragma unroll
    for (int nj = 0; nj < 8; nj++) {
        const int c = nj * 8 + 2 * tig;
        __half2 h0 = __floats2half2_rn(oacc[nj][0] * inv_top, oacc[nj][1] * inv_top);
        __half2 h1 = __floats2half2_rn(oacc[nj][2] * inv_bot, oacc[nj][3] * inv_bot);
        *(__half2*)(g_ao + ((size_t)(b * Nseq + n_top)) * (Hh * Dh) + h * Dh + c) = h0;
        *(__half2*)(g_ao + ((size_t)(b * Nseq + n_bot)) * (Hh * Dh) + h * Dh + c) = h1;
    }
}

// ---------------------------------------------------------------------------
extern "C" void kernel_launch(void* const* d_in, const int* in_sizes, int n_in,
                              void* d_out, int out_size)
{
    const float* x    = (const float*)d_in[0];
    const float* Wqkv = (const float*)d_in[1];
    const float* bqkv = (const float*)d_in[2];
    const float* Wout = (const float*)d_in[3];
    const float* bout = (const float*)d_in[4];
    float* out = (float*)d_out;

    // raise dynamic smem limits (idempotent)
    cudaFuncSetAttribute(gemm_f16_kernel<0>, cudaFuncAttributeMaxDynamicSharedMemorySize, 65536);
    cudaFuncSetAttribute(gemm_f16_kernel<1>, cudaFuncAttributeMaxDynamicSharedMemorySize, 65536);

    __half *gx, *gwq, *gwo;
    cudaGetSymbolAddress((void**)&gx,  g_x);
    cudaGetSymbolAddress((void**)&gwq, g_wq);
    cudaGetSymbolAddress((void**)&gwo, g_wo);

    // K0: fp16 pre-conversion (single launch)
    const int n1 = Bsz * Nseq * Emb / 4;
    const int n2 = 3 * Hh * Dh * Emb / 4;
    const int n3 = Emb * Hh * Dh / 4;
    cvt_f16_kernel<<<(n1 + n2 + n3 + 255) / 256, 256>>>(
        (const float4*)x, gx, n1,
        (const float4*)Wqkv, gwq, n2,
        (const float4*)Wout, gwo, n3);

    // K1: QKV projection + de-interleave scatter (Q x0.125, V transposed).
    gemm_f16_kernel<0><<<dim3(3072 / 128, 4096 / 128), 256, 65536>>>(bqkv, nullptr);

    // K2: causal flash attention. grid (N/64, B*H).
    flash_kernel<<<dim3(Nseq / 64, Bsz * Hh), 128>>>();

    // K3: output projection. C is [4096, 1024].
    gemm_f16_kernel<1><<<dim3(1024 / 128, 4096 / 128), 256, 65536>>>(bout, out);
}

// round 17
// speedup vs baseline: 2.4052x; 1.1933x over previous
#include <cuda_runtime.h>
#include <cuda_fp16.h>
#include <math.h>

#define Bsz  2
#define Nseq 2048
#define Emb  1024
#define Hh   16
#define Dh   64

// Scratch (allocation-free: __device__ globals) — all fp16
__device__ __half g_q [Bsz * Hh * Nseq * Dh];   // [B,H,N,D], pre-scaled by 0.125
__device__ __half g_k [Bsz * Hh * Nseq * Dh];   // [B,H,N,D]
__device__ __half g_v [Bsz * Hh * Nseq * Dh];   // [B,H,D,N]  (TRANSPOSED)
__device__ __half g_ao[Bsz * Nseq * Hh * Dh];   // [B,N,H*D]
__device__ __half g_x [Bsz * Nseq * Emb];
__device__ __half g_wq[3 * Hh * Dh * Emb];      // ROW-PERMUTED: [Q(h,d)|K(h,d)|V(h,d)]
__device__ __half g_wo[Emb * Hh * Dh];
__device__ float  g_bq[3 * Hh * Dh];            // permuted fp32 bias for K1

// ---------------------------------------------------------------------------
// helpers
// ---------------------------------------------------------------------------
__device__ __forceinline__ void mma_f16(float* c, const unsigned* a, const unsigned* b) {
    asm volatile(
        "mma.sync.aligned.m16n8k16.row.col.f32.f16.f16.f32 "
        "{%0,%1,%2,%3},{%4,%5,%6,%7},{%8,%9},{%0,%1,%2,%3};"
        : "+f"(c[0]), "+f"(c[1]), "+f"(c[2]), "+f"(c[3])
        : "r"(a[0]), "r"(a[1]), "r"(a[2]), "r"(a[3]), "r"(b[0]), "r"(b[1]));
}

__device__ __forceinline__ void ldsm_x4(unsigned& r0, unsigned& r1, unsigned& r2, unsigned& r3,
                                        unsigned saddr) {
    asm volatile("ldmatrix.sync.aligned.m8n8.x4.shared.b16 {%0,%1,%2,%3}, [%4];"
                 : "=r"(r0), "=r"(r1), "=r"(r2), "=r"(r3) : "r"(saddr));
}

__device__ __forceinline__ void cp16(void* dst_smem, const void* src_gmem) {
    unsigned d = (unsigned)__cvta_generic_to_shared(dst_smem);
    asm volatile("cp.async.cg.shared.global [%0], [%1], 16;" :: "r"(d), "l"(src_gmem));
}

__device__ __forceinline__ unsigned pk2(float lo, float hi) {
    __half2 h = __floats2half2_rn(lo, hi);
    return *reinterpret_cast<unsigned*>(&h);
}

// ---------------------------------------------------------------------------
// fp16 pre-convert pass. Wqkv rows are PERMUTED so K1's output columns are
// grouped [Q(h,d) | K(h,d) | V(h,d)]: new row j -> orig row h*192 + d*3 + r.
// Also produces the permuted fp32 bias g_bq.
// ---------------------------------------------------------------------------
__global__ void cvt_f16_kernel(const float4* __restrict__ x_in,  __half* __restrict__ x_out,  int n1,
                               const float4* __restrict__ wq_in, __half* __restrict__ wq_out, int n2,
                               const float4* __restrict__ wo_in, __half* __restrict__ wo_out, int n3,
                               const float*  __restrict__ bq_in)
{
    const int i = blockIdx.x * 256 + threadIdx.x;
    if (i < n1) {
        float4 v = x_in[i];
        __half2* d2 = (__half2*)(x_out + (size_t)i * 4);
        d2[0] = __floats2half2_rn(v.x, v.y);
        d2[1] = __floats2half2_rn(v.z, v.w);
    } else if (i < n1 + n2) {
        const int idx = i - n1;
        const int j = idx >> 8;            // new row (256 float4 per row)
        const int c = idx & 255;
        const int r = j >> 10, hh = (j >> 6) & 15, d = j & 63;
        const int orig = hh * 192 + d * 3 + r;
        float4 v = wq_in[orig * 256 + c];
        __half2* d2 = (__half2*)(wq_out + (size_t)idx * 4);
        d2[0] = __floats2half2_rn(v.x, v.y);
        d2[1] = __floats2half2_rn(v.z, v.w);
    } else if (i < n1 + n2 + n3) {
        const int idx = i - n1 - n2;
        float4 v = wo_in[idx];
        __half2* d2 = (__half2*)(wo_out + (size_t)idx * 4);
        d2[0] = __floats2half2_rn(v.x, v.y);
        d2[1] = __floats2half2_rn(v.z, v.w);
    } else if (i < n1 + n2 + n3 + 3 * Hh * Dh) {
        const int e = i - n1 - n2 - n3;
        const int r = e >> 10, hh = (e >> 6) & 15, d = e & 63;
        g_bq[e] = bq_in[hh * 192 + d * 3 + r];
    }
}

// ---------------------------------------------------------------------------
// FP16 GEMM: C[r][c] = sum_k A[r][k] * W[c][k] + bias[c]   (fp32 accum)
// 128x128 block tile, BK=64, 256 threads = 8 warps (4 x 2), warp tile 32x64.
// cp.async 2-stage pipeline, 128B-swizzled smem, ldmatrix, m16n8k16 HMMA.
// MODE 0 (permuted cols): Q/K via contiguous __half2 stores, V transposed
// scatter. MODE 1 writes fp32 out. Dynamic smem: 2 x 2 x 16KB = 64 KB.
// ---------------------------------------------------------------------------
template <int MODE>
__global__ void __launch_bounds__(256, 2) gemm_f16_kernel(const float* __restrict__ bias,
                                                          float* __restrict__ out)
{
    extern __shared__ __half hsm[];
    __half* Asm = hsm;            // 2 stages x 8192 halves
    __half* Wsm = hsm + 16384;    // 2 stages x 8192 halves

    const __half* Ain = (MODE == 0) ? g_x  : g_ao;
    const __half* Win = (MODE == 0) ? g_wq : g_wo;

    const int tid  = threadIdx.x;
    const int lane = tid & 31;
    const int warp = tid >> 5;
    const int wm   = warp & 3;         // 0..3 : 32-row group
    const int wn   = warp >> 2;        // 0..1 : 64-col group
    const int bm = blockIdx.y * 128;
    const int bn = blockIdx.x * 128;

    const int gid = lane >> 2;
    const int tig = lane & 3;

    // ldmatrix per-lane address components
    const int a_row  = lane & 15;
    const int a_cbit = lane >> 4;
    const int b_row  = (lane & 7) + ((lane & 16) >> 1);
    const int b_cbit = (lane >> 3) & 1;

    float acc[2][8][4];
#pragma unroll
    for (int mi = 0; mi < 2; mi++)
#pragma unroll
        for (int nj = 0; nj < 8; nj++)
#pragma unroll
            for (int q = 0; q < 4; q++) acc[mi][nj][q] = 0.f;

    auto cp_tile = [&](int kt, int stage) {
        const __half* Ab = Ain + (size_t)bm * Emb + kt * 64;
        const __half* Wb = Win + (size_t)bn * Emb + kt * 64;
        __half* as = Asm + stage * 8192;
        __half* ws = Wsm + stage * 8192;
#pragma unroll
        for (int i = 0; i < 4; i++) {
            const int idx = tid + i * 256;          // 0..1023
            const int row = idx >> 3;               // 0..127
            const int ch  = idx & 7;                // 16B chunk (8 halves)
            const int off = row * 64 + ((ch ^ (row & 7)) << 3);
            cp16(as + off, Ab + (size_t)row * Emb + ch * 8);
            cp16(ws + off, Wb + (size_t)row * Emb + ch * 8);
        }
        asm volatile("cp.async.commit_group;");
    };

    const int NT = Emb / 64;   // 16
    cp_tile(0, 0);

    for (int kt = 0; kt < NT; kt++) {
        if (kt + 1 < NT) {
            cp_tile(kt + 1, (kt + 1) & 1);
            asm volatile("cp.async.wait_group 1;");
        } else {
            asm volatile("cp.async.wait_group 0;");
        }
        __syncthreads();

        const __half* as = Asm + (kt & 1) * 8192;
        const __half* ws = Wsm + (kt & 1) * 8192;

#pragma unroll
        for (int ks = 0; ks < 4; ks++) {           // 4 x k16 = 64 K
            unsigned afrag[2][4];
#pragma unroll
            for (int mi = 0; mi < 2; mi++) {
                const int row = wm * 32 + mi * 16 + a_row;
                const int ch  = ks * 2 + a_cbit;
                const unsigned sa = (unsigned)__cvta_generic_to_shared(
                    as + row * 64 + ((ch ^ (row & 7)) << 3));
                ldsm_x4(afrag[mi][0], afrag[mi][1], afrag[mi][2], afrag[mi][3], sa);
            }
            unsigned bfrag[8][2];
#pragma unroll
            for (int nj2 = 0; nj2 < 4; nj2++) {
                const int row = wn * 64 + nj2 * 16 + b_row;
                const int ch  = ks * 2 + b_cbit;
                const unsigned sb = (unsigned)__cvta_generic_to_shared(
                    ws + row * 64 + ((ch ^ (row & 7)) << 3));
                ldsm_x4(bfrag[nj2 * 2][0], bfrag[nj2 * 2][1],
                        bfrag[nj2 * 2 + 1][0], bfrag[nj2 * 2 + 1][1], sb);
            }
#pragma unroll
            for (int mi = 0; mi < 2; mi++)
#pragma unroll
                for (int nj = 0; nj < 8; nj++)
                    mma_f16(acc[mi][nj], afrag[mi], bfrag[nj]);
        }
        __syncthreads();
    }

    // epilogue
#pragma unroll
    for (int mi = 0; mi < 2; mi++) {
        const int r_top = bm + wm * 32 + mi * 16 + gid;
        const int r_bot = r_top + 8;
#pragma unroll
        for (int nj = 0; nj < 8; nj++) {
            const int c = bn + wn * 64 + nj * 8 + 2 * tig;
            if (MODE == 0) {
                // permuted col space: c -> (region, h, d); c and c+1 share (region,h)
                const int reg = c >> 10;
                const int h   = (c >> 6) & 15;
                const int d   = c & 63;
                const float bv0 = g_bq[c], bv1 = g_bq[c + 1];
                float v0t = acc[mi][nj][0] + bv0, v1t = acc[mi][nj][1] + bv1;
                float v0b = acc[mi][nj][2] + bv0, v1b = acc[mi][nj][3] + bv1;
                const int b_t = r_top >> 11, n_t = r_top & 2047;
                const int b_b = r_bot >> 11, n_b = r_bot & 2047;
                if (reg == 0) {            // Q: x0.125, contiguous-d half2
                    v0t *= 0.125f; v1t *= 0.125f; v0b *= 0.125f; v1b *= 0.125f;
                    *(__half2*)(g_q + (((size_t)(b_t * Hh + h)) * Nseq + n_t) * Dh + d) =
                        __floats2half2_rn(v0t, v1t);
                    *(__half2*)(g_q + (((size_t)(b_b * Hh + h)) * Nseq + n_b) * Dh + d) =
                        __floats2half2_rn(v0b, v1b);
                } else if (reg == 1) {     // K: contiguous-d half2
                    *(__half2*)(g_k + (((size_t)(b_t * Hh + h)) * Nseq + n_t) * Dh + d) =
                        __floats2half2_rn(v0t, v1t);
                    *(__half2*)(g_k + (((size_t)(b_b * Hh + h)) * Nseq + n_b) * Dh + d) =
                        __floats2half2_rn(v0b, v1b);
                } else {                   // V transposed [B,H,D,N]
                    g_v[(((size_t)(b_t * Hh + h)) * Dh + d)     * Nseq + n_t] = __float2half_rn(v0t);
                    g_v[(((size_t)(b_t * Hh + h)) * Dh + d + 1) * Nseq + n_t] = __float2half_rn(v1t);
                    g_v[(((size_t)(b_b * Hh + h)) * Dh + d)     * Nseq + n_b] = __float2half_rn(v0b);
                    g_v[(((size_t)(b_b * Hh + h)) * Dh + d + 1) * Nseq + n_b] = __float2half_rn(v1b);
                }
            } else {
                const float2 bv = *(const float2*)(bias + c);
                float2 v0, v1;
                v0.x = acc[mi][nj][0] + bv.x; v0.y = acc[mi][nj][1] + bv.y;
                v1.x = acc[mi][nj][2] + bv.x; v1.y = acc[mi][nj][3] + bv.y;
                *(float2*)(out + (size_t)r_top * Emb + c) = v0;
                *(float2*)(out + (size_t)r_bot * Emb + c) = v1;
            }
        }
    }
}

// ---------------------------------------------------------------------------
// Flash attention v4 (fp16) — UNCHANGED from R16 (measured good).
// K/V/Q all cp.async swizzled tiles + ldmatrix, m16n8k16 HMMA, P in registers.
// grid = (N/64, B*H), 128 threads = 4 warps. BR=64, BC=32. Static smem 32KB.
// ---------------------------------------------------------------------------
__global__ void __launch_bounds__(128, 2) flash_kernel()
{
    __shared__ __half Qs[4096];        // 64 rows x 64 halves (128B rows)
    __shared__ __half Ks[2][2048];     // 32 rows x 64 halves
    __shared__ __half Vs[2][4096];     // 64 d-rows x 64 halves (32 seq used, padded)

    const int tid  = threadIdx.x;
    const int lane = tid & 31;
    const int w    = tid >> 5;
    const int gid  = lane >> 2;
    const int tig  = lane & 3;

    const int a_row  = lane & 15;
    const int a_cbit = lane >> 4;
    const int b_row  = (lane & 7) + ((lane & 16) >> 1);
    const int b_cbit = (lane >> 3) & 1;

    const int qb = (gridDim.x - 1) - blockIdx.x;   // heaviest blocks first
    const int bh = blockIdx.y;

    const __half* Qg = g_q + ((size_t)bh * Nseq + qb * 64) * Dh;
    const __half* Kg = g_k + (size_t)bh * Nseq * Dh;
    const __half* Vg = g_v + (size_t)bh * Dh * Nseq;   // transposed: rows=d

    const int ntiles = 2 * qb + 2;

    auto cp_k = [&](int j) {
        const __half* Kt = Kg + (size_t)j * 32 * Dh;
        __half* kb = Ks[j & 1];
#pragma unroll
        for (int i = 0; i < 2; i++) {
            const int idx = tid + i * 128;   // 0..255
            const int r   = idx >> 3;        // seq row 0..31
            const int ch  = idx & 7;
            cp16(kb + r * 64 + ((ch ^ (r & 7)) << 3), Kt + r * Dh + ch * 8);
        }
        asm volatile("cp.async.commit_group;");
    };
    auto cp_v = [&](int j) {
        const __half* Vt = Vg + (size_t)j * 32;
        __half* vb = Vs[j & 1];
#pragma unroll
        for (int i = 0; i < 2; i++) {
            const int idx = tid + i * 128;   // 0..255
            const int r   = idx >> 2;        // d row 0..63
            const int ch  = idx & 3;         // seq chunk 0..3
            cp16(vb + r * 64 + ((ch ^ (r & 7)) << 3), Vt + (size_t)r * Nseq + ch * 8);
        }
        asm volatile("cp.async.commit_group;");
    };

    // Q tile copy (pre-scaled by K1)
    {
#pragma unroll
        for (int i = 0; i < 4; i++) {
            const int idx = tid + i * 128;   // 0..511
            const int r   = idx >> 3;        // 0..63
            const int ch  = idx & 7;
            cp16(Qs + r * 64 + ((ch ^ (r & 7)) << 3), Qg + r * Dh + ch * 8);
        }
        asm volatile("cp.async.commit_group;");
    }
    cp_k(0);
    cp_v(0);

    float m_top = -INFINITY, m_bot = -INFINITY;
    float l_top = 0.f, l_bot = 0.f;

    float oacc[8][4];
#pragma unroll
    for (int nj = 0; nj < 8; nj++)
#pragma unroll
        for (int q = 0; q < 4; q++) oacc[nj][q] = 0.f;

    for (int j = 0; j < ntiles; j++) {
        const __half* kb = Ks[j & 1];
        const __half* vb = Vs[j & 1];

        asm volatile("cp.async.wait_group 0;");
        __syncthreads();
        if (j + 1 < ntiles) { cp_k(j + 1); cp_v(j + 1); }

        // ---- S = Q * K^T : m16 (warp rows) x n32, k=64 in 4 k16 steps ----
        float sacc[4][4];
#pragma unroll
        for (int nb = 0; nb < 4; nb++)
#pragma unroll
            for (int q = 0; q < 4; q++) sacc[nb][q] = 0.f;

#pragma unroll
        for (int ks = 0; ks < 4; ks++) {
            unsigned af[4];
            {
                const int row = w * 16 + a_row;
                const int ch  = ks * 2 + a_cbit;
                const unsigned sa = (unsigned)__cvta_generic_to_shared(
                    Qs + row * 64 + ((ch ^ (row & 7)) << 3));
                ldsm_x4(af[0], af[1], af[2], af[3], sa);
            }
            unsigned bf[4][2];
#pragma unroll
            for (int nb16 = 0; nb16 < 2; nb16++) {
                const int row = nb16 * 16 + b_row;
                const int ch  = ks * 2 + b_cbit;
                const unsigned sb = (unsigned)__cvta_generic_to_shared(
                    kb + row * 64 + ((ch ^ (row & 7)) << 3));
                ldsm_x4(bf[nb16 * 2][0], bf[nb16 * 2][1],
                        bf[nb16 * 2 + 1][0], bf[nb16 * 2 + 1][1], sb);
            }
#pragma unroll
            for (int nb = 0; nb < 4; nb++)
                mma_f16(sacc[nb], af, bf[nb]);
        }

        // causal mask
        if (j >= 2 * qb) {
            const int r0g = qb * 64 + w * 16 + gid;
            const int r1g = r0g + 8;
#pragma unroll
            for (int nb = 0; nb < 4; nb++) {
                const int cg = j * 32 + nb * 8 + 2 * tig;
                if (cg     > r0g) sacc[nb][0] = -INFINITY;
                if (cg + 1 > r0g) sacc[nb][1] = -INFINITY;
                if (cg     > r1g) sacc[nb][2] = -INFINITY;
                if (cg + 1 > r1g) sacc[nb][3] = -INFINITY;
            }
        }

        // ---- online softmax (quad shuffles), P packed into A-fragments ----
        float mt_t = m_top, mt_b = m_bot;
#pragma unroll
        for (int nb = 0; nb < 4; nb++) {
            mt_t = fmaxf(mt_t, fmaxf(sacc[nb][0], sacc[nb][1]));
            mt_b = fmaxf(mt_b, fmaxf(sacc[nb][2], sacc[nb][3]));
        }
        mt_t = fmaxf(mt_t, __shfl_xor_sync(0xffffffffu, mt_t, 1));
        mt_t = fmaxf(mt_t, __shfl_xor_sync(0xffffffffu, mt_t, 2));
        mt_b = fmaxf(mt_b, __shfl_xor_sync(0xffffffffu, mt_b, 1));
        mt_b = fmaxf(mt_b, __shfl_xor_sync(0xffffffffu, mt_b, 2));

        const bool nochange = (mt_t == m_top) && (mt_b == m_bot);
        const float sc_t = nochange ? 1.f : __expf(m_top - mt_t);
        const float sc_b = nochange ? 1.f : __expf(m_bot - mt_b);
        float ps_t = 0.f, ps_b = 0.f;

        unsigned paf[2][4];   // P A-fragments: [kstep][a0..a3]
#pragma unroll
        for (int nb = 0; nb < 4; nb++) {
            float p0 = __expf(sacc[nb][0] - mt_t);
            float p1 = __expf(sacc[nb][1] - mt_t);
            float p2 = __expf(sacc[nb][2] - mt_b);
            float p3 = __expf(sacc[nb][3] - mt_b);
            ps_t += p0 + p1;
            ps_b += p2 + p3;
            paf[nb >> 1][(nb & 1) * 2 + 0] = pk2(p0, p1);   // rows gid
            paf[nb >> 1][(nb & 1) * 2 + 1] = pk2(p2, p3);   // rows gid+8
        }
        ps_t += __shfl_xor_sync(0xffffffffu, ps_t, 1);
        ps_t += __shfl_xor_sync(0xffffffffu, ps_t, 2);
        ps_b += __shfl_xor_sync(0xffffffffu, ps_b, 1);
        ps_b += __shfl_xor_sync(0xffffffffu, ps_b, 2);

        l_top = l_top * sc_t + ps_t;  m_top = mt_t;
        l_bot = l_bot * sc_b + ps_b;  m_bot = mt_b;

        // ---- O = O*rescale + P*V (P from registers; V^T via ldmatrix) ----
        if (!__all_sync(0xffffffffu, nochange)) {
#pragma unroll
            for (int nj = 0; nj < 8; nj++) {
                oacc[nj][0] *= sc_t; oacc[nj][1] *= sc_t;
                oacc[nj][2] *= sc_b; oacc[nj][3] *= sc_b;
            }
        }
#pragma unroll
        for (int ks = 0; ks < 2; ks++) {           // k=seq32 in 2 k16 steps
            unsigned bf[8][2];
#pragma unroll
            for (int nj2 = 0; nj2 < 4; nj2++) {
                const int row = nj2 * 16 + b_row;  // d rows 0..63
                const int ch  = ks * 2 + b_cbit;   // seq chunks 0..3
                const unsigned sb = (unsigned)__cvta_generic_to_shared(
                    vb + row * 64 + ((ch ^ (row & 7)) << 3));
                ldsm_x4(bf[nj2 * 2][0], bf[nj2 * 2][1],
                        bf[nj2 * 2 + 1][0], bf[nj2 * 2 + 1][1], sb);
            }
#pragma unroll
            for (int nb = 0; nb < 8; nb++)
                mma_f16(oacc[nb], paf[ks], bf[nb]);
        }
        // no end-of-loop sync: next iteration's barrier orders buffer reuse
    }

    const int b = bh >> 4, h = bh & 15;
    const float inv_top = 1.f / l_top;
    const float inv_bot = 1.f / l_bot;
    const int n_top = qb * 64 + w * 16 + gid;
    const int n_bot = n_top + 8;
#pragma unroll
    for (int nj = 0; nj < 8; nj++) {
        const int c = nj * 8 + 2 * tig;
        __half2 h0 = __floats2half2_rn(oacc[nj][0] * inv_top, oacc[nj][1] * inv_top);
        __half2 h1 = __floats2half2_rn(oacc[nj][2] * inv_bot, oacc[nj][3] * inv_bot);
        *(__half2*)(g_ao + ((size_t)(b * Nseq + n_top)) * (Hh * Dh) + h * Dh + c) = h0;
        *(__half2*)(g_ao + ((size_t)(b * Nseq + n_bot)) * (Hh * Dh) + h * Dh + c) = h1;
    }
}

// ---------------------------------------------------------------------------
extern "C" void kernel_launch(void* const* d_in, const int* in_sizes, int n_in,
                              void* d_out, int out_size)
{
    const float* x    = (const float*)d_in[0];
    const float* Wqkv = (const float*)d_in[1];
    const float* bqkv = (const float*)d_in[2];
    const float* Wout = (const float*)d_in[3];
    const float* bout = (const float*)d_in[4];
    float* out = (float*)d_out;

    // raise dynamic smem limits (idempotent)
    cudaFuncSetAttribute(gemm_f16_kernel<0>, cudaFuncAttributeMaxDynamicSharedMemorySize, 65536);
    cudaFuncSetAttribute(gemm_f16_kernel<1>, cudaFuncAttributeMaxDynamicSharedMemorySize, 65536);

    __half *gx, *gwq, *gwo;
    cudaGetSymbolAddress((void**)&gx,  g_x);
    cudaGetSymbolAddress((void**)&gwq, g_wq);
    cudaGetSymbolAddress((void**)&gwo, g_wo);

    // K0: fp16 pre-conversion + Wqkv row permutation + permuted bias
    const int n1 = Bsz * Nseq * Emb / 4;
    const int n2 = 3 * Hh * Dh * Emb / 4;
    const int n3 = Emb * Hh * Dh / 4;
    const int ntot = n1 + n2 + n3 + 3 * Hh * Dh;
    cvt_f16_kernel<<<(ntot + 255) / 256, 256>>>(
        (const float4*)x, gx, n1,
        (const float4*)Wqkv, gwq, n2,
        (const float4*)Wout, gwo, n3,
        bqkv);

    // K1: QKV projection, grouped columns (Q x0.125, V transposed).
    gemm_f16_kernel<0><<<dim3(3072 / 128, 4096 / 128), 256, 65536>>>(nullptr, nullptr);

    // K2: causal flash attention. grid (N/64, B*H).
    flash_kernel<<<dim3(Nseq / 64, Bsz * Hh), 128>>>();

    // K3: output projection. C is [4096, 1024].
    gemm_f16_kernel<1><<<dim3(1024 / 128, 4096 / 128), 256, 65536>>>(bout, out);
}